// round 10
// baseline (speedup 1.0000x reference)
#include <cuda_runtime.h>
#include <cuda_bf16.h>
#include <math.h>
#include <stdint.h>

#define NN 512
#define CS 384
#define CZ 128
#define NH 8
#define CH 256
#define PQ_ 8
#define PV_ 12
#define FEAT 2688

// ---------------- scratch ----------------
__device__ float g_qbuf [NN * NH * CH];            // 512 x 2048
__device__ float g_kvbuf[NN * NH * 2 * CH];        // 512 x 4096
__device__ float g_qpraw[NN * NH * PQ_ * 3];       // 512 x 192
__device__ float g_kvpraw[NN * NH * (PQ_+PV_) * 3];// 512 x 480
__device__ float g_qpts [NN * NH * PQ_ * 3];       // [n][h*24 + p*3+d]
__device__ float g_kpts [NN * NH * PQ_ * 3];
__device__ float g_vpts [NN * NH * PV_ * 3];       // [n][h*36 + p*3+d]
__device__ float g_qnorm[NN * NH];
__device__ float g_knorm[NN * NH];
__device__ float g_biasz[(long)NH * NN * NN];      // [h][pair]
__device__ float g_pairz[(long)NN * NN * 32];      // [pair][32]
__device__ float g_logits[(long)NH * NN * NN];     // [h][i][j]
__device__ float g_optbuf[NH * NN * 36];           // [h][i][36]
__device__ float g_feats [NN * FEAT];
__device__ float g_part  [4 * NN * CS];            // split-K partials

// ---------------- tf32 helpers ----------------
__device__ __forceinline__ uint32_t to_tf32(float f) {
    uint32_t u;
    asm("cvt.rna.tf32.f32 %0, %1;" : "=r"(u) : "f"(f));
    return u;
}
__device__ __forceinline__ float tf32_hi(float x) {
    return __uint_as_float(to_tf32(x));
}
__device__ __forceinline__ void mma_tf32(float* c, const uint32_t* a, const uint32_t* b) {
    asm volatile(
        "mma.sync.aligned.m16n8k8.row.col.f32.tf32.tf32.f32 "
        "{%0,%1,%2,%3}, {%4,%5,%6,%7}, {%8,%9}, {%0,%1,%2,%3};"
        : "+f"(c[0]), "+f"(c[1]), "+f"(c[2]), "+f"(c[3])
        : "r"(a[0]), "r"(a[1]), "r"(a[2]), "r"(a[3]), "r"(b[0]), "r"(b[1]));
}

// 256 threads = 8 warps as 4x2; block tile 128x64; warp tile 32x32.
#define MMA_DECLS                                              \
    const int tid = threadIdx.x;                               \
    const int lane = tid & 31, wrp = tid >> 5;                 \
    const int wr = wrp >> 1, wc = wrp & 1;                     \
    const int gid = lane >> 2, tig = lane & 3;                 \
    const int rowb = wr * 32, colb = wc * 32;

#define MMA_TILE(As, Bs, acc)                                              \
    {                                                                      \
        _Pragma("unroll")                                                  \
        for (int ks = 0; ks < 2; ks++) {                                   \
            const int kb = ks * 8;                                         \
            uint32_t af[2][4], bf[4][2];                                   \
            _Pragma("unroll")                                              \
            for (int mi = 0; mi < 2; mi++) {                               \
                af[mi][0] = As[kb + tig][rowb + mi * 16 + gid];            \
                af[mi][1] = As[kb + tig][rowb + mi * 16 + gid + 8];        \
                af[mi][2] = As[kb + tig + 4][rowb + mi * 16 + gid];        \
                af[mi][3] = As[kb + tig + 4][rowb + mi * 16 + gid + 8];    \
            }                                                              \
            _Pragma("unroll")                                              \
            for (int ni = 0; ni < 4; ni++) {                               \
                bf[ni][0] = Bs[kb + tig][colb + ni * 8 + gid];             \
                bf[ni][1] = Bs[kb + tig + 4][colb + ni * 8 + gid];         \
            }                                                              \
            _Pragma("unroll")                                              \
            for (int mi = 0; mi < 2; mi++)                                 \
                _Pragma("unroll")                                          \
                for (int ni = 0; ni < 4; ni++)                             \
                    mma_tf32(acc[mi][ni], af[mi], bf[ni]);                 \
        }                                                                  \
    }

// ---------------- fused s projections (tensor) ----------------
__global__ __launch_bounds__(256) void proj_tc(
    const float* __restrict__ s,
    const float* __restrict__ wq,  const float* __restrict__ bq,
    const float* __restrict__ wkv, const float* __restrict__ bkv,
    const float* __restrict__ wqp, const float* __restrict__ bqp,
    const float* __restrict__ wkvp,const float* __restrict__ bkvp)
{
    __shared__ uint32_t As[16][136];
    __shared__ uint32_t Bs[16][72];
    MMA_DECLS;
    const int row0 = blockIdx.y * 128;
    const int bx = blockIdx.x;
    const int col0 = bx * 64;

    const float *B, *bias; float *Cb; int ldb, ldc, nseg, cb;
    if (bx < 32)      { B = wq;   ldb = 2048; bias = bq;   Cb = g_qbuf;   ldc = 2048; cb = col0;        nseg = 2048; }
    else if (bx < 96) { B = wkv;  ldb = 4096; bias = bkv;  Cb = g_kvbuf;  ldc = 4096; cb = col0 - 2048; nseg = 4096; }
    else if (bx < 99) { B = wqp;  ldb = 192;  bias = bqp;  Cb = g_qpraw;  ldc = 192;  cb = col0 - 6144; nseg = 192;  }
    else              { B = wkvp; ldb = 480;  bias = bkvp; Cb = g_kvpraw; ldc = 480;  cb = col0 - 6336; nseg = 480;  }

    float acc[2][4][4];
#pragma unroll
    for (int mi = 0; mi < 2; mi++)
#pragma unroll
        for (int ni = 0; ni < 4; ni++)
#pragma unroll
            for (int e = 0; e < 4; e++) acc[mi][ni][e] = 0.f;

    for (int k0 = 0; k0 < 384; k0 += 16) {
#pragma unroll
        for (int i = 0; i < 8; i++) {
            int idx = tid + i * 256;
            int r = idx >> 4, kk = idx & 15;
            As[kk][r] = to_tf32(s[(row0 + r) * 384 + k0 + kk]);
        }
#pragma unroll
        for (int i = 0; i < 4; i++) {
            int idx = tid + i * 256;
            int kk = idx >> 6, c = idx & 63;
            Bs[kk][c] = (cb + c < nseg) ? to_tf32(B[(long)(k0 + kk) * ldb + cb + c]) : 0u;
        }
        __syncthreads();
        MMA_TILE(As, Bs, acc);
        __syncthreads();
    }
#pragma unroll
    for (int mi = 0; mi < 2; mi++) {
        int r0 = row0 + rowb + mi * 16 + gid;
#pragma unroll
        for (int ni = 0; ni < 4; ni++) {
            int c0 = cb + colb + ni * 8 + 2 * tig;
#pragma unroll
            for (int e = 0; e < 4; e++) {
                int gr = r0 + (e >> 1) * 8;
                int cc = c0 + (e & 1);
                if (cc < nseg) Cb[(long)gr * ldc + cc] = acc[mi][ni][e] + bias[cc];
            }
        }
    }
}

// ---------------- rigid transform ----------------
__global__ void rigid_kernel(const float* __restrict__ rot,
                             const float* __restrict__ trans)
{
    int idx = blockIdx.x * 256 + threadIdx.x;
    if (idx >= NN * 224) return;
    int n = idx / 224, p = idx % 224;
    const float* R = rot + n * 9;
    const float* T = trans + n * 3;
    float lx, ly, lz;
    if (p < 64) {
        lx = g_qpraw[n * 192 + p];
        ly = g_qpraw[n * 192 + 64 + p];
        lz = g_qpraw[n * 192 + 128 + p];
    } else {
        int pp = p - 64;
        lx = g_kvpraw[n * 480 + pp];
        ly = g_kvpraw[n * 480 + 160 + pp];
        lz = g_kvpraw[n * 480 + 320 + pp];
    }
    float gx = R[0]*lx + R[1]*ly + R[2]*lz + T[0];
    float gy = R[3]*lx + R[4]*ly + R[5]*lz + T[1];
    float gz = R[6]*lx + R[7]*ly + R[8]*lz + T[2];
    if (p < 64) {
        int h = p >> 3, pq = p & 7;
        float* d = g_qpts + n * 192 + h * 24 + pq * 3;
        d[0] = gx; d[1] = gy; d[2] = gz;
    } else {
        int pp = p - 64;
        int h = pp / 20, q = pp % 20;
        if (q < 8) {
            float* d = g_kpts + n * 192 + h * 24 + q * 3;
            d[0] = gx; d[1] = gy; d[2] = gz;
        } else {
            float* d = g_vpts + n * 288 + h * 36 + (q - 8) * 3;
            d[0] = gx; d[1] = gy; d[2] = gz;
        }
    }
}

// ---------------- per (n,h) point-norm sums (exact fp32) ----------------
__global__ void pnorm_kernel()
{
    int idx = blockIdx.x * 256 + threadIdx.x;
    if (idx >= NN * NH) return;
    int n = idx >> 3, h = idx & 7;
    float sq = 0.f, sk = 0.f;
#pragma unroll
    for (int d = 0; d < 24; d++) {
        float a = g_qpts[n * 192 + h * 24 + d];
        float b = g_kpts[n * 192 + h * 24 + d];
        sq += a * a; sk += b * b;
    }
    g_qnorm[idx] = sq; g_knorm[idx] = sk;
}

// ---------------- z projections: ONE pass over z (tensor) ----------------
// GEMM: [262144 pairs x 128] @ [128 x 40]  -> biasz (8 cols) + pairz (32 cols)
__global__ __launch_bounds__(256) void zproj_tc(const float* __restrict__ z,
                             const float* __restrict__ wb, const float* __restrict__ bb,
                             const float* __restrict__ wz)
{
    __shared__ uint32_t As[16][136];
    __shared__ uint32_t Bs[16][72];
    MMA_DECLS;
    const long pair0 = (long)blockIdx.x * 128;

    float acc[2][4][4];
#pragma unroll
    for (int mi = 0; mi < 2; mi++)
#pragma unroll
        for (int ni = 0; ni < 4; ni++)
#pragma unroll
            for (int e = 0; e < 4; e++) acc[mi][ni][e] = 0.f;

    for (int k0 = 0; k0 < 128; k0 += 16) {
#pragma unroll
        for (int i = 0; i < 8; i++) {
            int idx = tid + i * 256;
            int r = idx >> 4, kk = idx & 15;
            As[kk][r] = to_tf32(z[(pair0 + r) * 128 + k0 + kk]);
        }
#pragma unroll
        for (int i = 0; i < 4; i++) {
            int idx = tid + i * 256;
            int kk = idx >> 6, c = idx & 63;
            uint32_t v = 0u;
            if (c < 8)       v = to_tf32(wb[(k0 + kk) * 8 + c]);
            else if (c < 40) v = to_tf32(wz[(k0 + kk) * 32 + (c - 8)]);
            Bs[kk][c] = v;
        }
        __syncthreads();
        MMA_TILE(As, Bs, acc);
        __syncthreads();
    }
#pragma unroll
    for (int mi = 0; mi < 2; mi++) {
        long r0 = pair0 + rowb + mi * 16 + gid;
#pragma unroll
        for (int ni = 0; ni < 4; ni++) {
            int c0 = colb + ni * 8 + 2 * tig;
#pragma unroll
            for (int e = 0; e < 4; e++) {
                long gp = r0 + (e >> 1) * 8;
                int cc = c0 + (e & 1);
                float v = acc[mi][ni][e];
                if (cc < 8)       g_biasz[(long)cc * 262144 + gp] = v + bb[cc];
                else if (cc < 40) g_pairz[gp * 32 + (cc - 8)] = v;
            }
        }
    }
}

// ---------------- logits: tensor QK + 2xTF32 point cross-term ----------------
__global__ __launch_bounds__(256) void logits_tc(const float* __restrict__ mask,
                              const float* __restrict__ head_w)
{
    const int h = blockIdx.z;
    __shared__ uint32_t As[16][136];
    __shared__ uint32_t Bs[16][72];
    __shared__ float qn_s[128], kn_s[64], mi_s[128], mj_s[64];
    MMA_DECLS;
    const int row0 = blockIdx.y * 128;
    const int col0 = blockIdx.x * 64;

    float w = head_w[h];
    float sp = (w > 20.f) ? w : log1pf(__expf(w));
    const float hw = sp * 0.09622504486493762f;    // softplus * sqrt(1/108)
    const float qscale = 0.036084391824351615f;    // sqrt(1/768)

    if (tid < 128) { qn_s[tid] = g_qnorm[(row0 + tid) * 8 + h]; mi_s[tid] = mask[row0 + tid]; }
    else if (tid < 192) { int c = tid - 128; kn_s[c] = g_knorm[(col0 + c) * 8 + h]; mj_s[c] = mask[col0 + c]; }

    float acc[2][4][4], accP[2][4][4];
#pragma unroll
    for (int mi = 0; mi < 2; mi++)
#pragma unroll
        for (int ni = 0; ni < 4; ni++)
#pragma unroll
            for (int e = 0; e < 4; e++) { acc[mi][ni][e] = 0.f; accP[mi][ni][e] = 0.f; }

    // phase 1: 256-dim QK (q pre-scaled)
    for (int k0 = 0; k0 < 256; k0 += 16) {
#pragma unroll
        for (int i = 0; i < 8; i++) {
            int idx = tid + i * 256;
            int r = idx >> 4, kk = idx & 15;
            As[kk][r] = to_tf32(g_qbuf[(row0 + r) * 2048 + h * 256 + k0 + kk] * qscale);
        }
#pragma unroll
        for (int i = 0; i < 4; i++) {
            int idx = tid + i * 256;
            int c = idx >> 4, kk = idx & 15;
            Bs[kk][c] = to_tf32(g_kvbuf[(col0 + c) * 4096 + h * 512 + k0 + kk]);
        }
        __syncthreads();
        MMA_TILE(As, Bs, acc);
        __syncthreads();
    }
    // phase 2: point cross-term, 24 dims x (hi*hi + lo*hi + hi*lo) = 72 (pad 80)
    for (int k0 = 0; k0 < 80; k0 += 16) {
#pragma unroll
        for (int i = 0; i < 8; i++) {
            int idx = tid + i * 256;
            int r = idx >> 4, kk = idx & 15;
            int cc = k0 + kk;
            uint32_t v = 0u;
            if (cc < 72) {
                int sel = cc / 24, pd = cc % 24;
                float x = g_qpts[(row0 + r) * 192 + h * 24 + pd];
                float hi = tf32_hi(x);
                v = (sel == 1) ? to_tf32(x - hi) : __float_as_uint(hi);
            }
            As[kk][r] = v;
        }
#pragma unroll
        for (int i = 0; i < 4; i++) {
            int idx = tid + i * 256;
            int c = idx >> 4, kk = idx & 15;
            int cc = k0 + kk;
            uint32_t v = 0u;
            if (cc < 72) {
                int sel = cc / 24, pd = cc % 24;
                float x = g_kpts[(col0 + c) * 192 + h * 24 + pd];
                float hi = tf32_hi(x);
                v = (sel == 2) ? to_tf32(x - hi) : __float_as_uint(hi);
            }
            Bs[kk][c] = v;
        }
        __syncthreads();
        MMA_TILE(As, Bs, accP);
        __syncthreads();
    }

#pragma unroll
    for (int mi = 0; mi < 2; mi++) {
#pragma unroll
        for (int ni = 0; ni < 4; ni++) {
#pragma unroll
            for (int e = 0; e < 4; e++) {
                int lr = rowb + mi * 16 + gid + (e >> 1) * 8;
                int lc = colb + ni * 8 + 2 * tig + (e & 1);
                int gr = row0 + lr, gc = col0 + lc;
                float v = acc[mi][ni][e]
                        + hw * accP[mi][ni][e]
                        - 0.5f * hw * (qn_s[lr] + kn_s[lc])
                        + 0.5773502691896258f * g_biasz[(long)h * 262144 + gr * 512 + gc]
                        + 100000.0f * (mi_s[lr] * mj_s[lc] - 1.0f);
                g_logits[((long)h * 512 + gr) * 512 + gc] = v;
            }
        }
    }
}

// ---------------- warp-per-row softmax ----------------
__global__ void softmax_kernel()
{
    int row = blockIdx.x * 8 + (threadIdx.x >> 5);
    int lane = threadIdx.x & 31;
    float* r = g_logits + (long)row * 512;
    float v[16];
    float m = -1e30f;
#pragma unroll
    for (int i = 0; i < 16; i++) { v[i] = r[lane + i * 32]; m = fmaxf(m, v[i]); }
#pragma unroll
    for (int s = 16; s > 0; s >>= 1) m = fmaxf(m, __shfl_xor_sync(0xffffffff, m, s));
    float sum = 0.f;
#pragma unroll
    for (int i = 0; i < 16; i++) { v[i] = __expf(v[i] - m); sum += v[i]; }
#pragma unroll
    for (int s = 16; s > 0; s >>= 1) sum += __shfl_xor_sync(0xffffffff, sum, s);
    float inv = 1.0f / sum;
#pragma unroll
    for (int i = 0; i < 16; i++) r[lane + i * 32] = v[i] * inv;
}

// ---------------- o = a @ v (tensor) ----------------
__global__ __launch_bounds__(256) void av_tc()
{
    const int h = blockIdx.z;
    __shared__ uint32_t As[16][136];
    __shared__ uint32_t Bs[16][72];
    MMA_DECLS;
    const int row0 = blockIdx.y * 128;
    const int col0 = blockIdx.x * 64;

    float acc[2][4][4];
#pragma unroll
    for (int mi = 0; mi < 2; mi++)
#pragma unroll
        for (int ni = 0; ni < 4; ni++)
#pragma unroll
            for (int e = 0; e < 4; e++) acc[mi][ni][e] = 0.f;

    for (int k0 = 0; k0 < 512; k0 += 16) {
#pragma unroll
        for (int i = 0; i < 8; i++) {
            int idx = tid + i * 256;
            int r = idx >> 4, kk = idx & 15;
            As[kk][r] = to_tf32(g_logits[((long)h * 512 + row0 + r) * 512 + k0 + kk]);
        }
#pragma unroll
        for (int i = 0; i < 4; i++) {
            int idx = tid + i * 256;
            int kk = idx >> 6, c = idx & 63;
            Bs[kk][c] = to_tf32(g_kvbuf[(k0 + kk) * 4096 + h * 512 + 256 + col0 + c]);
        }
        __syncthreads();
        MMA_TILE(As, Bs, acc);
        __syncthreads();
    }
#pragma unroll
    for (int mi = 0; mi < 2; mi++) {
        int r0 = row0 + rowb + mi * 16 + gid;
#pragma unroll
        for (int ni = 0; ni < 4; ni++) {
            int c0 = col0 + colb + ni * 8 + 2 * tig;
#pragma unroll
            for (int e = 0; e < 4; e++) {
                int gr = r0 + (e >> 1) * 8;
                int cc = c0 + (e & 1);
                g_feats[(long)gr * FEAT + h * 256 + cc] = acc[mi][ni][e];
            }
        }
    }
}

// ---------------- o_pt = a @ v_pts (fp32, cancellation-sensitive) ----------------
__global__ __launch_bounds__(288) void optgemm_kernel()
{
    __shared__ float a_s[8][512];
    __shared__ float vs[128][36];
    const int h = blockIdx.y;
    const int i0 = blockIdx.x * 8;
    const int t = threadIdx.x;
    for (int idx = t; idx < 4096; idx += 288) {
        int r = idx >> 9, k = idx & 511;
        a_s[r][k] = g_logits[((long)h * 512 + i0 + r) * 512 + k];
    }
    const int r = t / 36, c = t % 36;
    float acc = 0.f;
    for (int kc = 0; kc < 512; kc += 128) {
        __syncthreads();
        for (int idx = t; idx < 128 * 36; idx += 288) {
            int rr = idx / 36, cc = idx % 36;
            vs[rr][cc] = g_vpts[(kc + rr) * 288 + h * 36 + cc];
        }
        __syncthreads();
#pragma unroll 8
        for (int kk = 0; kk < 128; kk++) acc += a_s[r][kc + kk] * vs[kk][c];
    }
    g_optbuf[((long)h * 512 + i0 + r) * 36 + c] = acc;
}

// ---------------- o_pair = a @ pairz + bz (reads 33MB, not 134MB) ----------------
__global__ __launch_bounds__(256) void opair_kernel(const float* __restrict__ bz)
{
    __shared__ float a_s[8][512];
    const int i = blockIdx.x;
    const int t = threadIdx.x;
    for (int idx = t; idx < 4096; idx += 256) {
        int h = idx >> 9, j = idx & 511;
        a_s[h][j] = g_logits[((long)h * 512 + i) * 512 + j];
    }
    __syncthreads();
    const int h = t >> 5, d = t & 31;
    const float* pz = g_pairz + (long)i * 512 * 32 + d;
    float acc = 0.f;
#pragma unroll 8
    for (int j = 0; j < 512; j++) acc += a_s[h][j] * pz[(long)j * 32];
    g_feats[(long)i * FEAT + 2432 + h * 32 + d] = acc + bz[d];
}

// ---------------- o_pt inverse rigid + norm ----------------
__global__ void optfinal_kernel(const float* __restrict__ rot,
                                const float* __restrict__ trans)
{
    int idx = blockIdx.x * 256 + threadIdx.x;
    if (idx >= NN * 96) return;
    int n = idx / 96, hp = idx % 96;
    int h = hp / 12, p = hp % 12;
    const float* o = g_optbuf + ((long)h * 512 + n) * 36 + p * 3;
    float x = o[0] - trans[n * 3 + 0];
    float y = o[1] - trans[n * 3 + 1];
    float zc = o[2] - trans[n * 3 + 2];
    const float* R = rot + n * 9;
    float ox = R[0] * x + R[3] * y + R[6] * zc;
    float oy = R[1] * x + R[4] * y + R[7] * zc;
    float oz = R[2] * x + R[5] * y + R[8] * zc;
    float* f = g_feats + (long)n * FEAT;
    f[2048 + 0 * 96 + hp] = ox;
    f[2048 + 1 * 96 + hp] = oy;
    f[2048 + 2 * 96 + hp] = oz;
    f[2336 + hp] = sqrtf(ox * ox + oy * oy + oz * oz + 1e-8f);
}

// ---------------- final GEMM (tensor, split-K=4) ----------------
__global__ __launch_bounds__(256) void fingemm_tc(const float* __restrict__ wo)
{
    __shared__ uint32_t As[16][136];
    __shared__ uint32_t Bs[16][72];
    MMA_DECLS;
    const int row0 = blockIdx.y * 128;
    const int col0 = blockIdx.x * 64;
    const int kz = blockIdx.z;
    float* C = g_part + (long)kz * NN * CS;

    float acc[2][4][4];
#pragma unroll
    for (int mi = 0; mi < 2; mi++)
#pragma unroll
        for (int ni = 0; ni < 4; ni++)
#pragma unroll
            for (int e = 0; e < 4; e++) acc[mi][ni][e] = 0.f;

    for (int k0 = kz * 672; k0 < kz * 672 + 672; k0 += 16) {
#pragma unroll
        for (int i = 0; i < 8; i++) {
            int idx = tid + i * 256;
            int r = idx >> 4, kk = idx & 15;
            As[kk][r] = to_tf32(g_feats[(long)(row0 + r) * FEAT + k0 + kk]);
        }
#pragma unroll
        for (int i = 0; i < 4; i++) {
            int idx = tid + i * 256;
            int kk = idx >> 6, c = idx & 63;
            Bs[kk][c] = to_tf32(wo[(long)(k0 + kk) * 384 + col0 + c]);
        }
        __syncthreads();
        MMA_TILE(As, Bs, acc);
        __syncthreads();
    }
#pragma unroll
    for (int mi = 0; mi < 2; mi++) {
        int r0 = row0 + rowb + mi * 16 + gid;
#pragma unroll
        for (int ni = 0; ni < 4; ni++) {
            int c0 = col0 + colb + ni * 8 + 2 * tig;
#pragma unroll
            for (int e = 0; e < 4; e++)
                C[(long)(r0 + (e >> 1) * 8) * 384 + c0 + (e & 1)] = acc[mi][ni][e];
        }
    }
}

__global__ void reduce_kernel(const float* __restrict__ bo, float* __restrict__ out)
{
    int idx = blockIdx.x * 256 + threadIdx.x;
    if (idx >= NN * CS) return;
    float v = bo[idx % 384];
#pragma unroll
    for (int zc = 0; zc < 4; zc++) v += g_part[(long)zc * NN * CS + idx];
    out[idx] = v;
}

// ---------------- launch ----------------
extern "C" void kernel_launch(void* const* d_in, const int* in_sizes, int n_in,
                              void* d_out, int out_size)
{
    const float* s     = (const float*)d_in[0];
    const float* z     = (const float*)d_in[1];
    const float* rot   = (const float*)d_in[2];
    const float* trans = (const float*)d_in[3];
    const float* mask  = (const float*)d_in[4];
    const float* wq    = (const float*)d_in[5];
    const float* bq    = (const float*)d_in[6];
    const float* wkv   = (const float*)d_in[7];
    const float* bkv   = (const float*)d_in[8];
    const float* wqp   = (const float*)d_in[9];
    const float* bqp   = (const float*)d_in[10];
    const float* wkvp  = (const float*)d_in[11];
    const float* bkvp  = (const float*)d_in[12];
    const float* wb    = (const float*)d_in[13];
    const float* bb    = (const float*)d_in[14];
    const float* wz    = (const float*)d_in[15];
    const float* bz    = (const float*)d_in[16];
    const float* hwt   = (const float*)d_in[17];
    const float* wo    = (const float*)d_in[18];
    const float* bo    = (const float*)d_in[19];
    float* out = (float*)d_out;

    proj_tc<<<dim3(107, 4), 256>>>(s, wq, bq, wkv, bkv, wqp, bqp, wkvp, bkvp);
    rigid_kernel<<<(NN * 224 + 255) / 256, 256>>>(rot, trans);
    pnorm_kernel<<<(NN * NH + 255) / 256, 256>>>();
    zproj_tc<<<2048, 256>>>(z, wb, bb, wz);
    logits_tc<<<dim3(8, 4, 8), 256>>>(mask, hwt);
    softmax_kernel<<<512, 256>>>();
    av_tc<<<dim3(4, 4, 8), 256>>>();
    optgemm_kernel<<<dim3(64, 8), 288>>>();
    opair_kernel<<<NN, 256>>>(bz);
    optfinal_kernel<<<(NN * 96 + 255) / 256, 256>>>(rot, trans);
    fingemm_tc<<<dim3(6, 4, 4), 256>>>(wo);
    reduce_kernel<<<(NN * CS + 255) / 256, 256>>>(bo, out);
}

// round 11
// speedup vs baseline: 1.1758x; 1.1758x over previous
#include <cuda_runtime.h>
#include <cuda_bf16.h>
#include <math.h>
#include <stdint.h>

#define NN 512
#define CS 384
#define CZ 128
#define NH 8
#define CH 256
#define PQ_ 8
#define PV_ 12
#define FEAT 2688

// ---------------- scratch ----------------
__device__ float g_qbuf [NN * NH * CH];            // 512 x 2048
__device__ float g_kvbuf[NN * NH * 2 * CH];        // 512 x 4096
__device__ float g_qpraw[NN * NH * PQ_ * 3];       // 512 x 192
__device__ float g_kvpraw[NN * NH * (PQ_+PV_) * 3];// 512 x 480
__device__ float g_qpts [NN * NH * PQ_ * 3];       // [n][h*24 + p*3+d]
__device__ float g_kpts [NN * NH * PQ_ * 3];
__device__ float g_vpts [NN * NH * PV_ * 3];       // [n][h*36 + p*3+d]
__device__ float g_qnorm[NN * NH];
__device__ float g_knorm[NN * NH];
__device__ float g_biasz[(long)NH * NN * NN];      // [h][pair]
__device__ float g_pairz[(long)NN * NN * 32];      // [pair][32]
__device__ float g_logits[(long)NH * NN * NN];     // [h][i][j]
__device__ float g_optbuf[NH * NN * 36];           // [h][i][36]
__device__ float g_feats [NN * FEAT];
__device__ float g_part  [4 * NN * CS];            // split-K partials

// ---------------- tf32 helpers ----------------
__device__ __forceinline__ uint32_t to_tf32(float f) {
    uint32_t u;
    asm("cvt.rna.tf32.f32 %0, %1;" : "=r"(u) : "f"(f));
    return u;
}
__device__ __forceinline__ float tf32_hi(float x) {
    return __uint_as_float(to_tf32(x));
}
__device__ __forceinline__ void mma_tf32(float* c, const uint32_t* a, const uint32_t* b) {
    asm volatile(
        "mma.sync.aligned.m16n8k8.row.col.f32.tf32.tf32.f32 "
        "{%0,%1,%2,%3}, {%4,%5,%6,%7}, {%8,%9}, {%0,%1,%2,%3};"
        : "+f"(c[0]), "+f"(c[1]), "+f"(c[2]), "+f"(c[3])
        : "r"(a[0]), "r"(a[1]), "r"(a[2]), "r"(a[3]), "r"(b[0]), "r"(b[1]));
}

// 256 threads = 8 warps as 4x2; block tile 128x64; warp tile 32x32.
#define MMA_DECLS                                              \
    const int tid = threadIdx.x;                               \
    const int lane = tid & 31, wrp = tid >> 5;                 \
    const int wr = wrp >> 1, wc = wrp & 1;                     \
    const int gid = lane >> 2, tig = lane & 3;                 \
    const int rowb = wr * 32, colb = wc * 32;

#define MMA_TILE(As, Bs, acc)                                              \
    {                                                                      \
        _Pragma("unroll")                                                  \
        for (int ks = 0; ks < 2; ks++) {                                   \
            const int kb = ks * 8;                                         \
            uint32_t af[2][4], bf[4][2];                                   \
            _Pragma("unroll")                                              \
            for (int mi = 0; mi < 2; mi++) {                               \
                af[mi][0] = As[kb + tig][rowb + mi * 16 + gid];            \
                af[mi][1] = As[kb + tig][rowb + mi * 16 + gid + 8];        \
                af[mi][2] = As[kb + tig + 4][rowb + mi * 16 + gid];        \
                af[mi][3] = As[kb + tig + 4][rowb + mi * 16 + gid + 8];    \
            }                                                              \
            _Pragma("unroll")                                              \
            for (int ni = 0; ni < 4; ni++) {                               \
                bf[ni][0] = Bs[kb + tig][colb + ni * 8 + gid];             \
                bf[ni][1] = Bs[kb + tig + 4][colb + ni * 8 + gid];         \
            }                                                              \
            _Pragma("unroll")                                              \
            for (int mi = 0; mi < 2; mi++)                                 \
                _Pragma("unroll")                                          \
                for (int ni = 0; ni < 4; ni++)                             \
                    mma_tf32(acc[mi][ni], af[mi], bf[ni]);                 \
        }                                                                  \
    }

// ---------------- fused s projections (tensor) ----------------
__global__ __launch_bounds__(256) void proj_tc(
    const float* __restrict__ s,
    const float* __restrict__ wq,  const float* __restrict__ bq,
    const float* __restrict__ wkv, const float* __restrict__ bkv,
    const float* __restrict__ wqp, const float* __restrict__ bqp,
    const float* __restrict__ wkvp,const float* __restrict__ bkvp)
{
    __shared__ uint32_t As[16][136];
    __shared__ uint32_t Bs[16][72];
    MMA_DECLS;
    const int row0 = blockIdx.y * 128;
    const int bx = blockIdx.x;
    const int col0 = bx * 64;

    const float *B, *bias; float *Cb; int ldb, ldc, nseg, cb;
    if (bx < 32)      { B = wq;   ldb = 2048; bias = bq;   Cb = g_qbuf;   ldc = 2048; cb = col0;        nseg = 2048; }
    else if (bx < 96) { B = wkv;  ldb = 4096; bias = bkv;  Cb = g_kvbuf;  ldc = 4096; cb = col0 - 2048; nseg = 4096; }
    else if (bx < 99) { B = wqp;  ldb = 192;  bias = bqp;  Cb = g_qpraw;  ldc = 192;  cb = col0 - 6144; nseg = 192;  }
    else              { B = wkvp; ldb = 480;  bias = bkvp; Cb = g_kvpraw; ldc = 480;  cb = col0 - 6336; nseg = 480;  }

    float acc[2][4][4];
#pragma unroll
    for (int mi = 0; mi < 2; mi++)
#pragma unroll
        for (int ni = 0; ni < 4; ni++)
#pragma unroll
            for (int e = 0; e < 4; e++) acc[mi][ni][e] = 0.f;

    for (int k0 = 0; k0 < 384; k0 += 16) {
#pragma unroll
        for (int i = 0; i < 8; i++) {
            int idx = tid + i * 256;
            int r = idx >> 4, kk = idx & 15;
            As[kk][r] = to_tf32(s[(row0 + r) * 384 + k0 + kk]);
        }
#pragma unroll
        for (int i = 0; i < 4; i++) {
            int idx = tid + i * 256;
            int kk = idx >> 6, c = idx & 63;
            Bs[kk][c] = (cb + c < nseg) ? to_tf32(B[(long)(k0 + kk) * ldb + cb + c]) : 0u;
        }
        __syncthreads();
        MMA_TILE(As, Bs, acc);
        __syncthreads();
    }
#pragma unroll
    for (int mi = 0; mi < 2; mi++) {
        int r0 = row0 + rowb + mi * 16 + gid;
#pragma unroll
        for (int ni = 0; ni < 4; ni++) {
            int c0 = cb + colb + ni * 8 + 2 * tig;
#pragma unroll
            for (int e = 0; e < 4; e++) {
                int gr = r0 + (e >> 1) * 8;
                int cc = c0 + (e & 1);
                if (cc < nseg) Cb[(long)gr * ldc + cc] = acc[mi][ni][e] + bias[cc];
            }
        }
    }
}

// ---------------- rigid transform ----------------
__global__ void rigid_kernel(const float* __restrict__ rot,
                             const float* __restrict__ trans)
{
    int idx = blockIdx.x * 256 + threadIdx.x;
    if (idx >= NN * 224) return;
    int n = idx / 224, p = idx % 224;
    const float* R = rot + n * 9;
    const float* T = trans + n * 3;
    float lx, ly, lz;
    if (p < 64) {
        lx = g_qpraw[n * 192 + p];
        ly = g_qpraw[n * 192 + 64 + p];
        lz = g_qpraw[n * 192 + 128 + p];
    } else {
        int pp = p - 64;
        lx = g_kvpraw[n * 480 + pp];
        ly = g_kvpraw[n * 480 + 160 + pp];
        lz = g_kvpraw[n * 480 + 320 + pp];
    }
    float gx = R[0]*lx + R[1]*ly + R[2]*lz + T[0];
    float gy = R[3]*lx + R[4]*ly + R[5]*lz + T[1];
    float gz = R[6]*lx + R[7]*ly + R[8]*lz + T[2];
    if (p < 64) {
        int h = p >> 3, pq = p & 7;
        float* d = g_qpts + n * 192 + h * 24 + pq * 3;
        d[0] = gx; d[1] = gy; d[2] = gz;
    } else {
        int pp = p - 64;
        int h = pp / 20, q = pp % 20;
        if (q < 8) {
            float* d = g_kpts + n * 192 + h * 24 + q * 3;
            d[0] = gx; d[1] = gy; d[2] = gz;
        } else {
            float* d = g_vpts + n * 288 + h * 36 + (q - 8) * 3;
            d[0] = gx; d[1] = gy; d[2] = gz;
        }
    }
}

// ---------------- per (n,h) point-norm sums (exact fp32) ----------------
__global__ void pnorm_kernel()
{
    int idx = blockIdx.x * 256 + threadIdx.x;
    if (idx >= NN * NH) return;
    int n = idx >> 3, h = idx & 7;
    float sq = 0.f, sk = 0.f;
#pragma unroll
    for (int d = 0; d < 24; d++) {
        float a = g_qpts[n * 192 + h * 24 + d];
        float b = g_kpts[n * 192 + h * 24 + d];
        sq += a * a; sk += b * b;
    }
    g_qnorm[idx] = sq; g_knorm[idx] = sk;
}

// ---------------- z projections: ONE streaming tensor pass over z ----------------
// [262144 x 128] @ [128 x 40] -> biasz (cols 0..7) + pairz (cols 8..39)
// 256 pairs x 40 cols per block; weights staged once; float4/STS.128 staging.
// A row-major in smem, pad 36 (gid*4+tig covers all 32 banks -> conflict-free).
__global__ __launch_bounds__(256) void zproj_tc(const float* __restrict__ z,
                             const float* __restrict__ wb, const float* __restrict__ bb,
                             const float* __restrict__ wz)
{
    __shared__ uint32_t As[256][36];   // 36.9 KB
    __shared__ uint32_t Bs[128][40];   // 20.5 KB (40%8==0 -> conflict-free B frags)
    const int tid = threadIdx.x;
    const int lane = tid & 31, wrp = tid >> 5;
    const int gid = lane >> 2, tig = lane & 3;
    const long pair0 = (long)blockIdx.x * 256;
    const int rb = wrp * 32;

    // stage weights once
    for (int i = tid; i < 128 * 40; i += 256) {
        int k = i / 40, c = i % 40;
        float v = (c < 8) ? wb[k * 8 + c] : wz[k * 32 + (c - 8)];
        Bs[k][c] = to_tf32(v);
    }

    float acc[2][5][4];
#pragma unroll
    for (int mi = 0; mi < 2; mi++)
#pragma unroll
        for (int ni = 0; ni < 5; ni++)
#pragma unroll
            for (int e = 0; e < 4; e++) acc[mi][ni][e] = 0.f;

    for (int k0 = 0; k0 < 128; k0 += 32) {
        __syncthreads();   // As reuse guard (also orders Bs stores on first iter)
#pragma unroll
        for (int l = 0; l < 8; l++) {
            int q = tid + l * 256;          // 2048 float4 slots
            int r = q >> 3, kq = q & 7;     // 8 threads cover 128B of one row
            float4 v = *(const float4*)(z + (pair0 + r) * 128 + k0 + kq * 4);
            uint4 u = make_uint4(to_tf32(v.x), to_tf32(v.y), to_tf32(v.z), to_tf32(v.w));
            *(uint4*)&As[r][kq * 4] = u;
        }
        __syncthreads();
#pragma unroll
        for (int kb = 0; kb < 32; kb += 8) {
            uint32_t af[2][4], bf[5][2];
#pragma unroll
            for (int mi = 0; mi < 2; mi++) {
                af[mi][0] = As[rb + mi * 16 + gid][kb + tig];
                af[mi][1] = As[rb + mi * 16 + gid + 8][kb + tig];
                af[mi][2] = As[rb + mi * 16 + gid][kb + tig + 4];
                af[mi][3] = As[rb + mi * 16 + gid + 8][kb + tig + 4];
            }
#pragma unroll
            for (int ni = 0; ni < 5; ni++) {
                bf[ni][0] = Bs[k0 + kb + tig][ni * 8 + gid];
                bf[ni][1] = Bs[k0 + kb + tig + 4][ni * 8 + gid];
            }
#pragma unroll
            for (int mi = 0; mi < 2; mi++)
#pragma unroll
                for (int ni = 0; ni < 5; ni++)
                    mma_tf32(acc[mi][ni], af[mi], bf[ni]);
        }
    }

#pragma unroll
    for (int mi = 0; mi < 2; mi++) {
#pragma unroll
        for (int ni = 0; ni < 5; ni++) {
#pragma unroll
            for (int e = 0; e < 4; e++) {
                long gp = pair0 + rb + mi * 16 + gid + (e >> 1) * 8;
                int cc = ni * 8 + 2 * tig + (e & 1);
                float v = acc[mi][ni][e];
                if (cc < 8) g_biasz[(long)cc * 262144 + gp] = v + bb[cc];
                else        g_pairz[gp * 32 + (cc - 8)] = v;
            }
        }
    }
}

// ---------------- logits: tensor QK + 2xTF32 point cross-term ----------------
__global__ __launch_bounds__(256) void logits_tc(const float* __restrict__ mask,
                              const float* __restrict__ head_w)
{
    const int h = blockIdx.z;
    __shared__ uint32_t As[16][136];
    __shared__ uint32_t Bs[16][72];
    __shared__ float qn_s[128], kn_s[64], mi_s[128], mj_s[64];
    MMA_DECLS;
    const int row0 = blockIdx.y * 128;
    const int col0 = blockIdx.x * 64;

    float w = head_w[h];
    float sp = (w > 20.f) ? w : log1pf(__expf(w));
    const float hw = sp * 0.09622504486493762f;    // softplus * sqrt(1/108)
    const float qscale = 0.036084391824351615f;    // sqrt(1/768)

    if (tid < 128) { qn_s[tid] = g_qnorm[(row0 + tid) * 8 + h]; mi_s[tid] = mask[row0 + tid]; }
    else if (tid < 192) { int c = tid - 128; kn_s[c] = g_knorm[(col0 + c) * 8 + h]; mj_s[c] = mask[col0 + c]; }

    float acc[2][4][4], accP[2][4][4];
#pragma unroll
    for (int mi = 0; mi < 2; mi++)
#pragma unroll
        for (int ni = 0; ni < 4; ni++)
#pragma unroll
            for (int e = 0; e < 4; e++) { acc[mi][ni][e] = 0.f; accP[mi][ni][e] = 0.f; }

    // phase 1: 256-dim QK (q pre-scaled)
    for (int k0 = 0; k0 < 256; k0 += 16) {
#pragma unroll
        for (int i = 0; i < 8; i++) {
            int idx = tid + i * 256;
            int r = idx >> 4, kk = idx & 15;
            As[kk][r] = to_tf32(g_qbuf[(row0 + r) * 2048 + h * 256 + k0 + kk] * qscale);
        }
#pragma unroll
        for (int i = 0; i < 4; i++) {
            int idx = tid + i * 256;
            int c = idx >> 4, kk = idx & 15;
            Bs[kk][c] = to_tf32(g_kvbuf[(col0 + c) * 4096 + h * 512 + k0 + kk]);
        }
        __syncthreads();
        MMA_TILE(As, Bs, acc);
        __syncthreads();
    }
    // phase 2: point cross-term, 24 dims x (hi*hi + lo*hi + hi*lo) = 72 (pad 80)
    for (int k0 = 0; k0 < 80; k0 += 16) {
#pragma unroll
        for (int i = 0; i < 8; i++) {
            int idx = tid + i * 256;
            int r = idx >> 4, kk = idx & 15;
            int cc = k0 + kk;
            uint32_t v = 0u;
            if (cc < 72) {
                int sel = cc / 24, pd = cc % 24;
                float x = g_qpts[(row0 + r) * 192 + h * 24 + pd];
                float hi = tf32_hi(x);
                v = (sel == 1) ? to_tf32(x - hi) : __float_as_uint(hi);
            }
            As[kk][r] = v;
        }
#pragma unroll
        for (int i = 0; i < 4; i++) {
            int idx = tid + i * 256;
            int c = idx >> 4, kk = idx & 15;
            int cc = k0 + kk;
            uint32_t v = 0u;
            if (cc < 72) {
                int sel = cc / 24, pd = cc % 24;
                float x = g_kpts[(col0 + c) * 192 + h * 24 + pd];
                float hi = tf32_hi(x);
                v = (sel == 2) ? to_tf32(x - hi) : __float_as_uint(hi);
            }
            Bs[kk][c] = v;
        }
        __syncthreads();
        MMA_TILE(As, Bs, accP);
        __syncthreads();
    }

#pragma unroll
    for (int mi = 0; mi < 2; mi++) {
#pragma unroll
        for (int ni = 0; ni < 4; ni++) {
#pragma unroll
            for (int e = 0; e < 4; e++) {
                int lr = rowb + mi * 16 + gid + (e >> 1) * 8;
                int lc = colb + ni * 8 + 2 * tig + (e & 1);
                int gr = row0 + lr, gc = col0 + lc;
                float v = acc[mi][ni][e]
                        + hw * accP[mi][ni][e]
                        - 0.5f * hw * (qn_s[lr] + kn_s[lc])
                        + 0.5773502691896258f * g_biasz[(long)h * 262144 + gr * 512 + gc]
                        + 100000.0f * (mi_s[lr] * mj_s[lc] - 1.0f);
                g_logits[((long)h * 512 + gr) * 512 + gc] = v;
            }
        }
    }
}

// ---------------- warp-per-row softmax ----------------
__global__ void softmax_kernel()
{
    int row = blockIdx.x * 8 + (threadIdx.x >> 5);
    int lane = threadIdx.x & 31;
    float* r = g_logits + (long)row * 512;
    float v[16];
    float m = -1e30f;
#pragma unroll
    for (int i = 0; i < 16; i++) { v[i] = r[lane + i * 32]; m = fmaxf(m, v[i]); }
#pragma unroll
    for (int s = 16; s > 0; s >>= 1) m = fmaxf(m, __shfl_xor_sync(0xffffffff, m, s));
    float sum = 0.f;
#pragma unroll
    for (int i = 0; i < 16; i++) { v[i] = __expf(v[i] - m); sum += v[i]; }
#pragma unroll
    for (int s = 16; s > 0; s >>= 1) sum += __shfl_xor_sync(0xffffffff, sum, s);
    float inv = 1.0f / sum;
#pragma unroll
    for (int i = 0; i < 16; i++) r[lane + i * 32] = v[i] * inv;
}

// ---------------- o = a @ v (tensor) ----------------
__global__ __launch_bounds__(256) void av_tc()
{
    const int h = blockIdx.z;
    __shared__ uint32_t As[16][136];
    __shared__ uint32_t Bs[16][72];
    MMA_DECLS;
    const int row0 = blockIdx.y * 128;
    const int col0 = blockIdx.x * 64;

    float acc[2][4][4];
#pragma unroll
    for (int mi = 0; mi < 2; mi++)
#pragma unroll
        for (int ni = 0; ni < 4; ni++)
#pragma unroll
            for (int e = 0; e < 4; e++) acc[mi][ni][e] = 0.f;

    for (int k0 = 0; k0 < 512; k0 += 16) {
#pragma unroll
        for (int i = 0; i < 8; i++) {
            int idx = tid + i * 256;
            int r = idx >> 4, kk = idx & 15;
            As[kk][r] = to_tf32(g_logits[((long)h * 512 + row0 + r) * 512 + k0 + kk]);
        }
#pragma unroll
        for (int i = 0; i < 4; i++) {
            int idx = tid + i * 256;
            int kk = idx >> 6, c = idx & 63;
            Bs[kk][c] = to_tf32(g_kvbuf[(k0 + kk) * 4096 + h * 512 + 256 + col0 + c]);
        }
        __syncthreads();
        MMA_TILE(As, Bs, acc);
        __syncthreads();
    }
#pragma unroll
    for (int mi = 0; mi < 2; mi++) {
        int r0 = row0 + rowb + mi * 16 + gid;
#pragma unroll
        for (int ni = 0; ni < 4; ni++) {
            int c0 = col0 + colb + ni * 8 + 2 * tig;
#pragma unroll
            for (int e = 0; e < 4; e++) {
                int gr = r0 + (e >> 1) * 8;
                int cc = c0 + (e & 1);
                g_feats[(long)gr * FEAT + h * 256 + cc] = acc[mi][ni][e];
            }
        }
    }
}

// ---------------- o_pt = a @ v_pts (fp32, cancellation-sensitive) ----------------
__global__ __launch_bounds__(288) void optgemm_kernel()
{
    __shared__ float a_s[8][512];
    __shared__ float vs[128][36];
    const int h = blockIdx.y;
    const int i0 = blockIdx.x * 8;
    const int t = threadIdx.x;
    for (int idx = t; idx < 4096; idx += 288) {
        int r = idx >> 9, k = idx & 511;
        a_s[r][k] = g_logits[((long)h * 512 + i0 + r) * 512 + k];
    }
    const int r = t / 36, c = t % 36;
    float acc = 0.f;
    for (int kc = 0; kc < 512; kc += 128) {
        __syncthreads();
        for (int idx = t; idx < 128 * 36; idx += 288) {
            int rr = idx / 36, cc = idx % 36;
            vs[rr][cc] = g_vpts[(kc + rr) * 288 + h * 36 + cc];
        }
        __syncthreads();
#pragma unroll 8
        for (int kk = 0; kk < 128; kk++) acc += a_s[r][kc + kk] * vs[kk][c];
    }
    g_optbuf[((long)h * 512 + i0 + r) * 36 + c] = acc;
}

// ---------------- o_pair = a @ pairz + bz ----------------
__global__ __launch_bounds__(256) void opair_kernel(const float* __restrict__ bz)
{
    __shared__ float a_s[8][512];
    const int i = blockIdx.x;
    const int t = threadIdx.x;
    for (int idx = t; idx < 4096; idx += 256) {
        int h = idx >> 9, j = idx & 511;
        a_s[h][j] = g_logits[((long)h * 512 + i) * 512 + j];
    }
    __syncthreads();
    const int h = t >> 5, d = t & 31;
    const float* pz = g_pairz + (long)i * 512 * 32 + d;
    float acc = 0.f;
#pragma unroll 8
    for (int j = 0; j < 512; j++) acc += a_s[h][j] * pz[(long)j * 32];
    g_feats[(long)i * FEAT + 2432 + h * 32 + d] = acc + bz[d];
}

// ---------------- o_pt inverse rigid + norm ----------------
__global__ void optfinal_kernel(const float* __restrict__ rot,
                                const float* __restrict__ trans)
{
    int idx = blockIdx.x * 256 + threadIdx.x;
    if (idx >= NN * 96) return;
    int n = idx / 96, hp = idx % 96;
    int h = hp / 12, p = hp % 12;
    const float* o = g_optbuf + ((long)h * 512 + n) * 36 + p * 3;
    float x = o[0] - trans[n * 3 + 0];
    float y = o[1] - trans[n * 3 + 1];
    float zc = o[2] - trans[n * 3 + 2];
    const float* R = rot + n * 9;
    float ox = R[0] * x + R[3] * y + R[6] * zc;
    float oy = R[1] * x + R[4] * y + R[7] * zc;
    float oz = R[2] * x + R[5] * y + R[8] * zc;
    float* f = g_feats + (long)n * FEAT;
    f[2048 + 0 * 96 + hp] = ox;
    f[2048 + 1 * 96 + hp] = oy;
    f[2048 + 2 * 96 + hp] = oz;
    f[2336 + hp] = sqrtf(ox * ox + oy * oy + oz * oz + 1e-8f);
}

// ---------------- final GEMM (tensor, split-K=4) ----------------
__global__ __launch_bounds__(256) void fingemm_tc(const float* __restrict__ wo)
{
    __shared__ uint32_t As[16][136];
    __shared__ uint32_t Bs[16][72];
    MMA_DECLS;
    const int row0 = blockIdx.y * 128;
    const int col0 = blockIdx.x * 64;
    const int kz = blockIdx.z;
    float* C = g_part + (long)kz * NN * CS;

    float acc[2][4][4];
#pragma unroll
    for (int mi = 0; mi < 2; mi++)
#pragma unroll
        for (int ni = 0; ni < 4; ni++)
#pragma unroll
            for (int e = 0; e < 4; e++) acc[mi][ni][e] = 0.f;

    for (int k0 = kz * 672; k0 < kz * 672 + 672; k0 += 16) {
#pragma unroll
        for (int i = 0; i < 8; i++) {
            int idx = tid + i * 256;
            int r = idx >> 4, kk = idx & 15;
            As[kk][r] = to_tf32(g_feats[(long)(row0 + r) * FEAT + k0 + kk]);
        }
#pragma unroll
        for (int i = 0; i < 4; i++) {
            int idx = tid + i * 256;
            int kk = idx >> 6, c = idx & 63;
            Bs[kk][c] = to_tf32(wo[(long)(k0 + kk) * 384 + col0 + c]);
        }
        __syncthreads();
        MMA_TILE(As, Bs, acc);
        __syncthreads();
    }
#pragma unroll
    for (int mi = 0; mi < 2; mi++) {
        int r0 = row0 + rowb + mi * 16 + gid;
#pragma unroll
        for (int ni = 0; ni < 4; ni++) {
            int c0 = col0 + colb + ni * 8 + 2 * tig;
#pragma unroll
            for (int e = 0; e < 4; e++)
                C[(long)(r0 + (e >> 1) * 8) * 384 + c0 + (e & 1)] = acc[mi][ni][e];
        }
    }
}

__global__ void reduce_kernel(const float* __restrict__ bo, float* __restrict__ out)
{
    int idx = blockIdx.x * 256 + threadIdx.x;
    if (idx >= NN * CS) return;
    float v = bo[idx % 384];
#pragma unroll
    for (int zc = 0; zc < 4; zc++) v += g_part[(long)zc * NN * CS + idx];
    out[idx] = v;
}

// ---------------- launch ----------------
extern "C" void kernel_launch(void* const* d_in, const int* in_sizes, int n_in,
                              void* d_out, int out_size)
{
    const float* s     = (const float*)d_in[0];
    const float* z     = (const float*)d_in[1];
    const float* rot   = (const float*)d_in[2];
    const float* trans = (const float*)d_in[3];
    const float* mask  = (const float*)d_in[4];
    const float* wq    = (const float*)d_in[5];
    const float* bq    = (const float*)d_in[6];
    const float* wkv   = (const float*)d_in[7];
    const float* bkv   = (const float*)d_in[8];
    const float* wqp   = (const float*)d_in[9];
    const float* bqp   = (const float*)d_in[10];
    const float* wkvp  = (const float*)d_in[11];
    const float* bkvp  = (const float*)d_in[12];
    const float* wb    = (const float*)d_in[13];
    const float* bb    = (const float*)d_in[14];
    const float* wz    = (const float*)d_in[15];
    const float* bz    = (const float*)d_in[16];
    const float* hwt   = (const float*)d_in[17];
    const float* wo    = (const float*)d_in[18];
    const float* bo    = (const float*)d_in[19];
    float* out = (float*)d_out;

    proj_tc<<<dim3(107, 4), 256>>>(s, wq, bq, wkv, bkv, wqp, bqp, wkvp, bkvp);
    rigid_kernel<<<(NN * 224 + 255) / 256, 256>>>(rot, trans);
    pnorm_kernel<<<(NN * NH + 255) / 256, 256>>>();
    zproj_tc<<<1024, 256>>>(z, wb, bb, wz);
    logits_tc<<<dim3(8, 4, 8), 256>>>(mask, hwt);
    softmax_kernel<<<512, 256>>>();
    av_tc<<<dim3(4, 4, 8), 256>>>();
    optgemm_kernel<<<dim3(64, 8), 288>>>();
    opair_kernel<<<NN, 256>>>(bz);
    optfinal_kernel<<<(NN * 96 + 255) / 256, 256>>>(rot, trans);
    fingemm_tc<<<dim3(6, 4, 4), 256>>>(wo);
    reduce_kernel<<<(NN * CS + 255) / 256, 256>>>(bo, out);
}

// round 12
// speedup vs baseline: 1.2320x; 1.0478x over previous
#include <cuda_runtime.h>
#include <cuda_bf16.h>
#include <math.h>
#include <stdint.h>

#define NN 512
#define CS 384
#define CZ 128
#define NH 8
#define CH 256
#define PQ_ 8
#define PV_ 12
#define FEAT 2688

// ---------------- scratch ----------------
__device__ float g_qbuf [NN * NH * CH];            // 512 x 2048
__device__ float g_kvbuf[NN * NH * 2 * CH];        // 512 x 4096
__device__ float g_qpraw[NN * NH * PQ_ * 3];       // 512 x 192
__device__ float g_kvpraw[NN * NH * (PQ_+PV_) * 3];// 512 x 480
__device__ float g_qpts [NN * NH * PQ_ * 3];       // [n][h*24 + p*3+d]
__device__ float g_kpts [NN * NH * PQ_ * 3];
__device__ float g_vpts [NN * NH * PV_ * 3];       // [n][h*36 + p*3+d]
__device__ float g_qnorm[NN * NH];
__device__ float g_knorm[NN * NH];
__device__ float g_biasz[(long)NH * NN * NN];      // [h][pair]
__device__ float g_pairz[(long)NN * NN * 32];      // [pair][32]
__device__ float g_logits[(long)NH * NN * NN];     // [h][i][j]
__device__ float g_optbuf[NH * NN * 36];           // [h][i][36]
__device__ float g_feats [NN * FEAT];
__device__ float g_part  [4 * NN * CS];            // split-K partials

// ---------------- tf32 helpers ----------------
__device__ __forceinline__ uint32_t to_tf32(float f) {
    uint32_t u;
    asm("cvt.rna.tf32.f32 %0, %1;" : "=r"(u) : "f"(f));
    return u;
}
__device__ __forceinline__ float tf32_hi(float x) {
    return __uint_as_float(to_tf32(x));
}
__device__ __forceinline__ void mma_tf32(float* c, const uint32_t* a, const uint32_t* b) {
    asm volatile(
        "mma.sync.aligned.m16n8k8.row.col.f32.tf32.tf32.f32 "
        "{%0,%1,%2,%3}, {%4,%5,%6,%7}, {%8,%9}, {%0,%1,%2,%3};"
        : "+f"(c[0]), "+f"(c[1]), "+f"(c[2]), "+f"(c[3])
        : "r"(a[0]), "r"(a[1]), "r"(a[2]), "r"(a[3]), "r"(b[0]), "r"(b[1]));
}

// 256 threads = 8 warps as 4x2; block tile 128x64; warp tile 32x32.
#define MMA_DECLS                                              \
    const int tid = threadIdx.x;                               \
    const int lane = tid & 31, wrp = tid >> 5;                 \
    const int wr = wrp >> 1, wc = wrp & 1;                     \
    const int gid = lane >> 2, tig = lane & 3;                 \
    const int rowb = wr * 32, colb = wc * 32;

#define MMA_TILE(As, Bs, acc)                                              \
    {                                                                      \
        _Pragma("unroll")                                                  \
        for (int ks = 0; ks < 2; ks++) {                                   \
            const int kb = ks * 8;                                         \
            uint32_t af[2][4], bf[4][2];                                   \
            _Pragma("unroll")                                              \
            for (int mi = 0; mi < 2; mi++) {                               \
                af[mi][0] = As[kb + tig][rowb + mi * 16 + gid];            \
                af[mi][1] = As[kb + tig][rowb + mi * 16 + gid + 8];        \
                af[mi][2] = As[kb + tig + 4][rowb + mi * 16 + gid];        \
                af[mi][3] = As[kb + tig + 4][rowb + mi * 16 + gid + 8];    \
            }                                                              \
            _Pragma("unroll")                                              \
            for (int ni = 0; ni < 4; ni++) {                               \
                bf[ni][0] = Bs[kb + tig][colb + ni * 8 + gid];             \
                bf[ni][1] = Bs[kb + tig + 4][colb + ni * 8 + gid];         \
            }                                                              \
            _Pragma("unroll")                                              \
            for (int mi = 0; mi < 2; mi++)                                 \
                _Pragma("unroll")                                          \
                for (int ni = 0; ni < 4; ni++)                             \
                    mma_tf32(acc[mi][ni], af[mi], bf[ni]);                 \
        }                                                                  \
    }

// ---------------- fused s projections (tensor) ----------------
__global__ __launch_bounds__(256) void proj_tc(
    const float* __restrict__ s,
    const float* __restrict__ wq,  const float* __restrict__ bq,
    const float* __restrict__ wkv, const float* __restrict__ bkv,
    const float* __restrict__ wqp, const float* __restrict__ bqp,
    const float* __restrict__ wkvp,const float* __restrict__ bkvp)
{
    __shared__ uint32_t As[16][136];
    __shared__ uint32_t Bs[16][72];
    MMA_DECLS;
    const int row0 = blockIdx.y * 128;
    const int bx = blockIdx.x;
    const int col0 = bx * 64;

    const float *B, *bias; float *Cb; int ldb, ldc, nseg, cb;
    if (bx < 32)      { B = wq;   ldb = 2048; bias = bq;   Cb = g_qbuf;   ldc = 2048; cb = col0;        nseg = 2048; }
    else if (bx < 96) { B = wkv;  ldb = 4096; bias = bkv;  Cb = g_kvbuf;  ldc = 4096; cb = col0 - 2048; nseg = 4096; }
    else if (bx < 99) { B = wqp;  ldb = 192;  bias = bqp;  Cb = g_qpraw;  ldc = 192;  cb = col0 - 6144; nseg = 192;  }
    else              { B = wkvp; ldb = 480;  bias = bkvp; Cb = g_kvpraw; ldc = 480;  cb = col0 - 6336; nseg = 480;  }

    float acc[2][4][4];
#pragma unroll
    for (int mi = 0; mi < 2; mi++)
#pragma unroll
        for (int ni = 0; ni < 4; ni++)
#pragma unroll
            for (int e = 0; e < 4; e++) acc[mi][ni][e] = 0.f;

    for (int k0 = 0; k0 < 384; k0 += 16) {
#pragma unroll
        for (int i = 0; i < 8; i++) {
            int idx = tid + i * 256;
            int r = idx >> 4, kk = idx & 15;
            As[kk][r] = to_tf32(s[(row0 + r) * 384 + k0 + kk]);
        }
#pragma unroll
        for (int i = 0; i < 4; i++) {
            int idx = tid + i * 256;
            int kk = idx >> 6, c = idx & 63;
            Bs[kk][c] = (cb + c < nseg) ? to_tf32(B[(long)(k0 + kk) * ldb + cb + c]) : 0u;
        }
        __syncthreads();
        MMA_TILE(As, Bs, acc);
        __syncthreads();
    }
#pragma unroll
    for (int mi = 0; mi < 2; mi++) {
        int r0 = row0 + rowb + mi * 16 + gid;
#pragma unroll
        for (int ni = 0; ni < 4; ni++) {
            int c0 = cb + colb + ni * 8 + 2 * tig;
#pragma unroll
            for (int e = 0; e < 4; e++) {
                int gr = r0 + (e >> 1) * 8;
                int cc = c0 + (e & 1);
                if (cc < nseg) Cb[(long)gr * ldc + cc] = acc[mi][ni][e] + bias[cc];
            }
        }
    }
}

// ---------------- rigid transform ----------------
__global__ void rigid_kernel(const float* __restrict__ rot,
                             const float* __restrict__ trans)
{
    int idx = blockIdx.x * 256 + threadIdx.x;
    if (idx >= NN * 224) return;
    int n = idx / 224, p = idx % 224;
    const float* R = rot + n * 9;
    const float* T = trans + n * 3;
    float lx, ly, lz;
    if (p < 64) {
        lx = g_qpraw[n * 192 + p];
        ly = g_qpraw[n * 192 + 64 + p];
        lz = g_qpraw[n * 192 + 128 + p];
    } else {
        int pp = p - 64;
        lx = g_kvpraw[n * 480 + pp];
        ly = g_kvpraw[n * 480 + 160 + pp];
        lz = g_kvpraw[n * 480 + 320 + pp];
    }
    float gx = R[0]*lx + R[1]*ly + R[2]*lz + T[0];
    float gy = R[3]*lx + R[4]*ly + R[5]*lz + T[1];
    float gz = R[6]*lx + R[7]*ly + R[8]*lz + T[2];
    if (p < 64) {
        int h = p >> 3, pq = p & 7;
        float* d = g_qpts + n * 192 + h * 24 + pq * 3;
        d[0] = gx; d[1] = gy; d[2] = gz;
    } else {
        int pp = p - 64;
        int h = pp / 20, q = pp % 20;
        if (q < 8) {
            float* d = g_kpts + n * 192 + h * 24 + q * 3;
            d[0] = gx; d[1] = gy; d[2] = gz;
        } else {
            float* d = g_vpts + n * 288 + h * 36 + (q - 8) * 3;
            d[0] = gx; d[1] = gy; d[2] = gz;
        }
    }
}

// ---------------- per (n,h) point-norm sums (exact fp32) ----------------
__global__ void pnorm_kernel()
{
    int idx = blockIdx.x * 256 + threadIdx.x;
    if (idx >= NN * NH) return;
    int n = idx >> 3, h = idx & 7;
    float sq = 0.f, sk = 0.f;
#pragma unroll
    for (int d = 0; d < 24; d++) {
        float a = g_qpts[n * 192 + h * 24 + d];
        float b = g_kpts[n * 192 + h * 24 + d];
        sq += a * a; sk += b * b;
    }
    g_qnorm[idx] = sq; g_knorm[idx] = sk;
}

// ---------------- z projections: cp.async double-buffered streaming GEMM ----------------
// [262144 x 128] @ [128 x 40] -> biasz (cols 0..7) + pairz (cols 8..39)
// 128 pairs x 40 cols per block, grid 2048. z streamed via cp.async (raw fp32
// bits fed to tf32 MMA -> HW truncation, <=1ulp(tf32) vs cvt.rna).
__global__ __launch_bounds__(256) void zproj_tc(const float* __restrict__ z,
                             const float* __restrict__ wb, const float* __restrict__ bb,
                             const float* __restrict__ wz)
{
    __shared__ float    As[2][128][36];   // 36.9 KB (pad 36 -> conflict-free frags)
    __shared__ uint32_t Bs[128][40];      // 20.5 KB
    const int tid = threadIdx.x;
    const int lane = tid & 31, wrp = tid >> 5;
    const int gid = lane >> 2, tig = lane & 3;
    const long pair0 = (long)blockIdx.x * 128;
    const int rb = wrp * 16;              // each warp: 16 rows x 40 cols

    // stage weights once (tf32 rounded)
    for (int i = tid; i < 128 * 40; i += 256) {
        int k = i / 40, c = i % 40;
        float v = (c < 8) ? wb[k * 8 + c] : wz[k * 32 + (c - 8)];
        Bs[k][c] = to_tf32(v);
    }

    // async stage of one 128x32 chunk into buffer buf
#define ZSTAGE(buf, k0)                                                        \
    {                                                                          \
        _Pragma("unroll")                                                      \
        for (int l = 0; l < 4; l++) {                                          \
            int q = tid + l * 256;                                             \
            int r = q >> 3, kq = q & 7;                                        \
            uint32_t dst = (uint32_t)__cvta_generic_to_shared(&As[buf][r][kq * 4]); \
            const float* src = z + (pair0 + r) * 128 + (k0) + kq * 4;          \
            asm volatile("cp.async.cg.shared.global [%0], [%1], 16;" :: "r"(dst), "l"(src)); \
        }                                                                      \
        asm volatile("cp.async.commit_group;");                                \
    }

    ZSTAGE(0, 0);

    float acc[5][4];
#pragma unroll
    for (int ni = 0; ni < 5; ni++)
#pragma unroll
        for (int e = 0; e < 4; e++) acc[ni][e] = 0.f;

#pragma unroll
    for (int c = 0; c < 4; c++) {
        const int buf = c & 1;
        if (c < 3) ZSTAGE((c + 1) & 1, (c + 1) * 32);
        if (c < 3) { asm volatile("cp.async.wait_group 1;"); }
        else       { asm volatile("cp.async.wait_group 0;"); }
        __syncthreads();
#pragma unroll
        for (int kb = 0; kb < 32; kb += 8) {
            uint32_t af[4], bf[5][2];
            af[0] = __float_as_uint(As[buf][rb + gid][kb + tig]);
            af[1] = __float_as_uint(As[buf][rb + gid + 8][kb + tig]);
            af[2] = __float_as_uint(As[buf][rb + gid][kb + tig + 4]);
            af[3] = __float_as_uint(As[buf][rb + gid + 8][kb + tig + 4]);
#pragma unroll
            for (int ni = 0; ni < 5; ni++) {
                bf[ni][0] = Bs[c * 32 + kb + tig][ni * 8 + gid];
                bf[ni][1] = Bs[c * 32 + kb + tig + 4][ni * 8 + gid];
            }
#pragma unroll
            for (int ni = 0; ni < 5; ni++)
                mma_tf32(acc[ni], af, bf[ni]);
        }
        __syncthreads();   // protect buf from being overwritten by next stage
    }
#undef ZSTAGE

#pragma unroll
    for (int ni = 0; ni < 5; ni++) {
#pragma unroll
        for (int e = 0; e < 4; e++) {
            long gp = pair0 + rb + gid + (e >> 1) * 8;
            int cc = ni * 8 + 2 * tig + (e & 1);
            float v = acc[ni][e];
            if (cc < 8) g_biasz[(long)cc * 262144 + gp] = v + bb[cc];
            else        g_pairz[gp * 32 + (cc - 8)] = v;
        }
    }
}

// ---------------- logits: tensor QK + 2xTF32 point cross-term ----------------
__global__ __launch_bounds__(256) void logits_tc(const float* __restrict__ mask,
                              const float* __restrict__ head_w)
{
    const int h = blockIdx.z;
    __shared__ uint32_t As[16][136];
    __shared__ uint32_t Bs[16][72];
    __shared__ float qn_s[128], kn_s[64], mi_s[128], mj_s[64];
    MMA_DECLS;
    const int row0 = blockIdx.y * 128;
    const int col0 = blockIdx.x * 64;

    float w = head_w[h];
    float sp = (w > 20.f) ? w : log1pf(__expf(w));
    const float hw = sp * 0.09622504486493762f;    // softplus * sqrt(1/108)
    const float qscale = 0.036084391824351615f;    // sqrt(1/768)

    if (tid < 128) { qn_s[tid] = g_qnorm[(row0 + tid) * 8 + h]; mi_s[tid] = mask[row0 + tid]; }
    else if (tid < 192) { int c = tid - 128; kn_s[c] = g_knorm[(col0 + c) * 8 + h]; mj_s[c] = mask[col0 + c]; }

    float acc[2][4][4], accP[2][4][4];
#pragma unroll
    for (int mi = 0; mi < 2; mi++)
#pragma unroll
        for (int ni = 0; ni < 4; ni++)
#pragma unroll
            for (int e = 0; e < 4; e++) { acc[mi][ni][e] = 0.f; accP[mi][ni][e] = 0.f; }

    // phase 1: 256-dim QK (q pre-scaled)
    for (int k0 = 0; k0 < 256; k0 += 16) {
#pragma unroll
        for (int i = 0; i < 8; i++) {
            int idx = tid + i * 256;
            int r = idx >> 4, kk = idx & 15;
            As[kk][r] = to_tf32(g_qbuf[(row0 + r) * 2048 + h * 256 + k0 + kk] * qscale);
        }
#pragma unroll
        for (int i = 0; i < 4; i++) {
            int idx = tid + i * 256;
            int c = idx >> 4, kk = idx & 15;
            Bs[kk][c] = to_tf32(g_kvbuf[(col0 + c) * 4096 + h * 512 + k0 + kk]);
        }
        __syncthreads();
        MMA_TILE(As, Bs, acc);
        __syncthreads();
    }
    // phase 2: point cross-term, 24 dims x (hi*hi + lo*hi + hi*lo) = 72 (pad 80)
    for (int k0 = 0; k0 < 80; k0 += 16) {
#pragma unroll
        for (int i = 0; i < 8; i++) {
            int idx = tid + i * 256;
            int r = idx >> 4, kk = idx & 15;
            int cc = k0 + kk;
            uint32_t v = 0u;
            if (cc < 72) {
                int sel = cc / 24, pd = cc % 24;
                float x = g_qpts[(row0 + r) * 192 + h * 24 + pd];
                float hi = tf32_hi(x);
                v = (sel == 1) ? to_tf32(x - hi) : __float_as_uint(hi);
            }
            As[kk][r] = v;
        }
#pragma unroll
        for (int i = 0; i < 4; i++) {
            int idx = tid + i * 256;
            int c = idx >> 4, kk = idx & 15;
            int cc = k0 + kk;
            uint32_t v = 0u;
            if (cc < 72) {
                int sel = cc / 24, pd = cc % 24;
                float x = g_kpts[(col0 + c) * 192 + h * 24 + pd];
                float hi = tf32_hi(x);
                v = (sel == 2) ? to_tf32(x - hi) : __float_as_uint(hi);
            }
            Bs[kk][c] = v;
        }
        __syncthreads();
        MMA_TILE(As, Bs, accP);
        __syncthreads();
    }

#pragma unroll
    for (int mi = 0; mi < 2; mi++) {
#pragma unroll
        for (int ni = 0; ni < 4; ni++) {
#pragma unroll
            for (int e = 0; e < 4; e++) {
                int lr = rowb + mi * 16 + gid + (e >> 1) * 8;
                int lc = colb + ni * 8 + 2 * tig + (e & 1);
                int gr = row0 + lr, gc = col0 + lc;
                float v = acc[mi][ni][e]
                        + hw * accP[mi][ni][e]
                        - 0.5f * hw * (qn_s[lr] + kn_s[lc])
                        + 0.5773502691896258f * g_biasz[(long)h * 262144 + gr * 512 + gc]
                        + 100000.0f * (mi_s[lr] * mj_s[lc] - 1.0f);
                g_logits[((long)h * 512 + gr) * 512 + gc] = v;
            }
        }
    }
}

// ---------------- warp-per-row softmax ----------------
__global__ void softmax_kernel()
{
    int row = blockIdx.x * 8 + (threadIdx.x >> 5);
    int lane = threadIdx.x & 31;
    float* r = g_logits + (long)row * 512;
    float v[16];
    float m = -1e30f;
#pragma unroll
    for (int i = 0; i < 16; i++) { v[i] = r[lane + i * 32]; m = fmaxf(m, v[i]); }
#pragma unroll
    for (int s = 16; s > 0; s >>= 1) m = fmaxf(m, __shfl_xor_sync(0xffffffff, m, s));
    float sum = 0.f;
#pragma unroll
    for (int i = 0; i < 16; i++) { v[i] = __expf(v[i] - m); sum += v[i]; }
#pragma unroll
    for (int s = 16; s > 0; s >>= 1) sum += __shfl_xor_sync(0xffffffff, sum, s);
    float inv = 1.0f / sum;
#pragma unroll
    for (int i = 0; i < 16; i++) r[lane + i * 32] = v[i] * inv;
}

// ---------------- o = a @ v (tensor) ----------------
__global__ __launch_bounds__(256) void av_tc()
{
    const int h = blockIdx.z;
    __shared__ uint32_t As[16][136];
    __shared__ uint32_t Bs[16][72];
    MMA_DECLS;
    const int row0 = blockIdx.y * 128;
    const int col0 = blockIdx.x * 64;

    float acc[2][4][4];
#pragma unroll
    for (int mi = 0; mi < 2; mi++)
#pragma unroll
        for (int ni = 0; ni < 4; ni++)
#pragma unroll
            for (int e = 0; e < 4; e++) acc[mi][ni][e] = 0.f;

    for (int k0 = 0; k0 < 512; k0 += 16) {
#pragma unroll
        for (int i = 0; i < 8; i++) {
            int idx = tid + i * 256;
            int r = idx >> 4, kk = idx & 15;
            As[kk][r] = to_tf32(g_logits[((long)h * 512 + row0 + r) * 512 + k0 + kk]);
        }
#pragma unroll
        for (int i = 0; i < 4; i++) {
            int idx = tid + i * 256;
            int kk = idx >> 6, c = idx & 63;
            Bs[kk][c] = to_tf32(g_kvbuf[(k0 + kk) * 4096 + h * 512 + 256 + col0 + c]);
        }
        __syncthreads();
        MMA_TILE(As, Bs, acc);
        __syncthreads();
    }
#pragma unroll
    for (int mi = 0; mi < 2; mi++) {
        int r0 = row0 + rowb + mi * 16 + gid;
#pragma unroll
        for (int ni = 0; ni < 4; ni++) {
            int c0 = col0 + colb + ni * 8 + 2 * tig;
#pragma unroll
            for (int e = 0; e < 4; e++) {
                int gr = r0 + (e >> 1) * 8;
                int cc = c0 + (e & 1);
                g_feats[(long)gr * FEAT + h * 256 + cc] = acc[mi][ni][e];
            }
        }
    }
}

// ---------------- o_pt = a @ v_pts (fp32, cancellation-sensitive) ----------------
__global__ __launch_bounds__(288) void optgemm_kernel()
{
    __shared__ float a_s[8][512];
    __shared__ float vs[128][36];
    const int h = blockIdx.y;
    const int i0 = blockIdx.x * 8;
    const int t = threadIdx.x;
    for (int idx = t; idx < 4096; idx += 288) {
        int r = idx >> 9, k = idx & 511;
        a_s[r][k] = g_logits[((long)h * 512 + i0 + r) * 512 + k];
    }
    const int r = t / 36, c = t % 36;
    float acc = 0.f;
    for (int kc = 0; kc < 512; kc += 128) {
        __syncthreads();
        for (int idx = t; idx < 128 * 36; idx += 288) {
            int rr = idx / 36, cc = idx % 36;
            vs[rr][cc] = g_vpts[(kc + rr) * 288 + h * 36 + cc];
        }
        __syncthreads();
#pragma unroll 8
        for (int kk = 0; kk < 128; kk++) acc += a_s[r][kc + kk] * vs[kk][c];
    }
    g_optbuf[((long)h * 512 + i0 + r) * 36 + c] = acc;
}

// ---------------- o_pair = a @ pairz + bz ----------------
__global__ __launch_bounds__(256) void opair_kernel(const float* __restrict__ bz)
{
    __shared__ float a_s[8][512];
    const int i = blockIdx.x;
    const int t = threadIdx.x;
    for (int idx = t; idx < 4096; idx += 256) {
        int h = idx >> 9, j = idx & 511;
        a_s[h][j] = g_logits[((long)h * 512 + i) * 512 + j];
    }
    __syncthreads();
    const int h = t >> 5, d = t & 31;
    const float* pz = g_pairz + (long)i * 512 * 32 + d;
    float acc = 0.f;
#pragma unroll 8
    for (int j = 0; j < 512; j++) acc += a_s[h][j] * pz[(long)j * 32];
    g_feats[(long)i * FEAT + 2432 + h * 32 + d] = acc + bz[d];
}

// ---------------- o_pt inverse rigid + norm ----------------
__global__ void optfinal_kernel(const float* __restrict__ rot,
                                const float* __restrict__ trans)
{
    int idx = blockIdx.x * 256 + threadIdx.x;
    if (idx >= NN * 96) return;
    int n = idx / 96, hp = idx % 96;
    int h = hp / 12, p = hp % 12;
    const float* o = g_optbuf + ((long)h * 512 + n) * 36 + p * 3;
    float x = o[0] - trans[n * 3 + 0];
    float y = o[1] - trans[n * 3 + 1];
    float zc = o[2] - trans[n * 3 + 2];
    const float* R = rot + n * 9;
    float ox = R[0] * x + R[3] * y + R[6] * zc;
    float oy = R[1] * x + R[4] * y + R[7] * zc;
    float oz = R[2] * x + R[5] * y + R[8] * zc;
    float* f = g_feats + (long)n * FEAT;
    f[2048 + 0 * 96 + hp] = ox;
    f[2048 + 1 * 96 + hp] = oy;
    f[2048 + 2 * 96 + hp] = oz;
    f[2336 + hp] = sqrtf(ox * ox + oy * oy + oz * oz + 1e-8f);
}

// ---------------- final GEMM (tensor, split-K=4) ----------------
__global__ __launch_bounds__(256) void fingemm_tc(const float* __restrict__ wo)
{
    __shared__ uint32_t As[16][136];
    __shared__ uint32_t Bs[16][72];
    MMA_DECLS;
    const int row0 = blockIdx.y * 128;
    const int col0 = blockIdx.x * 64;
    const int kz = blockIdx.z;
    float* C = g_part + (long)kz * NN * CS;

    float acc[2][4][4];
#pragma unroll
    for (int mi = 0; mi < 2; mi++)
#pragma unroll
        for (int ni = 0; ni < 4; ni++)
#pragma unroll
            for (int e = 0; e < 4; e++) acc[mi][ni][e] = 0.f;

    for (int k0 = kz * 672; k0 < kz * 672 + 672; k0 += 16) {
#pragma unroll
        for (int i = 0; i < 8; i++) {
            int idx = tid + i * 256;
            int r = idx >> 4, kk = idx & 15;
            As[kk][r] = to_tf32(g_feats[(long)(row0 + r) * FEAT + k0 + kk]);
        }
#pragma unroll
        for (int i = 0; i < 4; i++) {
            int idx = tid + i * 256;
            int kk = idx >> 6, c = idx & 63;
            Bs[kk][c] = to_tf32(wo[(long)(k0 + kk) * 384 + col0 + c]);
        }
        __syncthreads();
        MMA_TILE(As, Bs, acc);
        __syncthreads();
    }
#pragma unroll
    for (int mi = 0; mi < 2; mi++) {
        int r0 = row0 + rowb + mi * 16 + gid;
#pragma unroll
        for (int ni = 0; ni < 4; ni++) {
            int c0 = col0 + colb + ni * 8 + 2 * tig;
#pragma unroll
            for (int e = 0; e < 4; e++)
                C[(long)(r0 + (e >> 1) * 8) * 384 + c0 + (e & 1)] = acc[mi][ni][e];
        }
    }
}

__global__ void reduce_kernel(const float* __restrict__ bo, float* __restrict__ out)
{
    int idx = blockIdx.x * 256 + threadIdx.x;
    if (idx >= NN * CS) return;
    float v = bo[idx % 384];
#pragma unroll
    for (int zc = 0; zc < 4; zc++) v += g_part[(long)zc * NN * CS + idx];
    out[idx] = v;
}

// ---------------- launch ----------------
extern "C" void kernel_launch(void* const* d_in, const int* in_sizes, int n_in,
                              void* d_out, int out_size)
{
    const float* s     = (const float*)d_in[0];
    const float* z     = (const float*)d_in[1];
    const float* rot   = (const float*)d_in[2];
    const float* trans = (const float*)d_in[3];
    const float* mask  = (const float*)d_in[4];
    const float* wq    = (const float*)d_in[5];
    const float* bq    = (const float*)d_in[6];
    const float* wkv   = (const float*)d_in[7];
    const float* bkv   = (const float*)d_in[8];
    const float* wqp   = (const float*)d_in[9];
    const float* bqp   = (const float*)d_in[10];
    const float* wkvp  = (const float*)d_in[11];
    const float* bkvp  = (const float*)d_in[12];
    const float* wb    = (const float*)d_in[13];
    const float* bb    = (const float*)d_in[14];
    const float* wz    = (const float*)d_in[15];
    const float* bz    = (const float*)d_in[16];
    const float* hwt   = (const float*)d_in[17];
    const float* wo    = (const float*)d_in[18];
    const float* bo    = (const float*)d_in[19];
    float* out = (float*)d_out;

    proj_tc<<<dim3(107, 4), 256>>>(s, wq, bq, wkv, bkv, wqp, bqp, wkvp, bkvp);
    rigid_kernel<<<(NN * 224 + 255) / 256, 256>>>(rot, trans);
    pnorm_kernel<<<(NN * NH + 255) / 256, 256>>>();
    zproj_tc<<<2048, 256>>>(z, wb, bb, wz);
    logits_tc<<<dim3(8, 4, 8), 256>>>(mask, hwt);
    softmax_kernel<<<512, 256>>>();
    av_tc<<<dim3(4, 4, 8), 256>>>();
    optgemm_kernel<<<dim3(64, 8), 288>>>();
    opair_kernel<<<NN, 256>>>(bz);
    optfinal_kernel<<<(NN * 96 + 255) / 256, 256>>>(rot, trans);
    fingemm_tc<<<dim3(6, 4, 4), 256>>>(wo);
    reduce_kernel<<<(NN * CS + 255) / 256, 256>>>(bo, out);
}

// round 14
// speedup vs baseline: 1.2324x; 1.0003x over previous
#include <cuda_runtime.h>
#include <cuda_bf16.h>
#include <math.h>
#include <stdint.h>

#define NN 512
#define CS 384
#define CZ 128
#define NH 8
#define CH 256
#define PQ_ 8
#define PV_ 12
#define FEAT 2688

// ---------------- scratch ----------------
__device__ float g_qbuf [NN * NH * CH];            // 512 x 2048
__device__ float g_kvbuf[NN * NH * 2 * CH];        // 512 x 4096
__device__ float g_qpraw[NN * NH * PQ_ * 3];       // 512 x 192
__device__ float g_kvpraw[NN * NH * (PQ_+PV_) * 3];// 512 x 480
__device__ float g_qpts [NN * NH * PQ_ * 3];       // [n][h*24 + p*3+d]
__device__ float g_kpts [NN * NH * PQ_ * 3];
__device__ float g_vpts [NN * NH * PV_ * 3];       // [n][h*36 + p*3+d]
__device__ float g_qnorm[NN * NH];
__device__ float g_knorm[NN * NH];
__device__ float g_biasz[(long)NH * NN * NN];      // [h][pair]
__device__ float g_pairz[(long)NN * NN * 32];      // [pair][32]
__device__ float g_logits[(long)NH * NN * NN];     // [h][i][j]
__device__ float g_optbuf[NH * NN * 36];           // [h][i][36]
__device__ float g_feats [NN * FEAT];
__device__ float g_part  [4 * NN * CS];            // split-K partials

// ---------------- tf32 helpers ----------------
__device__ __forceinline__ uint32_t to_tf32(float f) {
    uint32_t u;
    asm("cvt.rna.tf32.f32 %0, %1;" : "=r"(u) : "f"(f));
    return u;
}
__device__ __forceinline__ float tf32_hi(float x) {
    return __uint_as_float(to_tf32(x));
}
__device__ __forceinline__ void mma_tf32(float* c, const uint32_t* a, const uint32_t* b) {
    asm volatile(
        "mma.sync.aligned.m16n8k8.row.col.f32.tf32.tf32.f32 "
        "{%0,%1,%2,%3}, {%4,%5,%6,%7}, {%8,%9}, {%0,%1,%2,%3};"
        : "+f"(c[0]), "+f"(c[1]), "+f"(c[2]), "+f"(c[3])
        : "r"(a[0]), "r"(a[1]), "r"(a[2]), "r"(a[3]), "r"(b[0]), "r"(b[1]));
}

// 256 threads = 8 warps as 4x2; block tile 128x64; warp tile 32x32.
#define MMA_DECLS                                              \
    const int tid = threadIdx.x;                               \
    const int lane = tid & 31, wrp = tid >> 5;                 \
    const int wr = wrp >> 1, wc = wrp & 1;                     \
    const int gid = lane >> 2, tig = lane & 3;                 \
    const int rowb = wr * 32, colb = wc * 32;

#define MMA_TILE(As, Bs, acc)                                              \
    {                                                                      \
        _Pragma("unroll")                                                  \
        for (int ks = 0; ks < 2; ks++) {                                   \
            const int kb = ks * 8;                                         \
            uint32_t af[2][4], bf[4][2];                                   \
            _Pragma("unroll")                                              \
            for (int mi = 0; mi < 2; mi++) {                               \
                af[mi][0] = As[kb + tig][rowb + mi * 16 + gid];            \
                af[mi][1] = As[kb + tig][rowb + mi * 16 + gid + 8];        \
                af[mi][2] = As[kb + tig + 4][rowb + mi * 16 + gid];        \
                af[mi][3] = As[kb + tig + 4][rowb + mi * 16 + gid + 8];    \
            }                                                              \
            _Pragma("unroll")                                              \
            for (int ni = 0; ni < 4; ni++) {                               \
                bf[ni][0] = Bs[kb + tig][colb + ni * 8 + gid];             \
                bf[ni][1] = Bs[kb + tig + 4][colb + ni * 8 + gid];         \
            }                                                              \
            _Pragma("unroll")                                              \
            for (int mi = 0; mi < 2; mi++)                                 \
                _Pragma("unroll")                                          \
                for (int ni = 0; ni < 4; ni++)                             \
                    mma_tf32(acc[mi][ni], af[mi], bf[ni]);                 \
        }                                                                  \
    }

// ---------------- fused s projections (tensor) ----------------
__global__ __launch_bounds__(256) void proj_tc(
    const float* __restrict__ s,
    const float* __restrict__ wq,  const float* __restrict__ bq,
    const float* __restrict__ wkv, const float* __restrict__ bkv,
    const float* __restrict__ wqp, const float* __restrict__ bqp,
    const float* __restrict__ wkvp,const float* __restrict__ bkvp)
{
    __shared__ uint32_t As[16][136];
    __shared__ uint32_t Bs[16][72];
    MMA_DECLS;
    const int row0 = blockIdx.y * 128;
    const int bx = blockIdx.x;
    const int col0 = bx * 64;

    const float *B, *bias; float *Cb; int ldb, ldc, nseg, cb;
    if (bx < 32)      { B = wq;   ldb = 2048; bias = bq;   Cb = g_qbuf;   ldc = 2048; cb = col0;        nseg = 2048; }
    else if (bx < 96) { B = wkv;  ldb = 4096; bias = bkv;  Cb = g_kvbuf;  ldc = 4096; cb = col0 - 2048; nseg = 4096; }
    else if (bx < 99) { B = wqp;  ldb = 192;  bias = bqp;  Cb = g_qpraw;  ldc = 192;  cb = col0 - 6144; nseg = 192;  }
    else              { B = wkvp; ldb = 480;  bias = bkvp; Cb = g_kvpraw; ldc = 480;  cb = col0 - 6336; nseg = 480;  }

    float acc[2][4][4];
#pragma unroll
    for (int mi = 0; mi < 2; mi++)
#pragma unroll
        for (int ni = 0; ni < 4; ni++)
#pragma unroll
            for (int e = 0; e < 4; e++) acc[mi][ni][e] = 0.f;

    for (int k0 = 0; k0 < 384; k0 += 16) {
#pragma unroll
        for (int i = 0; i < 8; i++) {
            int idx = tid + i * 256;
            int r = idx >> 4, kk = idx & 15;
            As[kk][r] = to_tf32(s[(row0 + r) * 384 + k0 + kk]);
        }
#pragma unroll
        for (int i = 0; i < 4; i++) {
            int idx = tid + i * 256;
            int kk = idx >> 6, c = idx & 63;
            Bs[kk][c] = (cb + c < nseg) ? to_tf32(B[(long)(k0 + kk) * ldb + cb + c]) : 0u;
        }
        __syncthreads();
        MMA_TILE(As, Bs, acc);
        __syncthreads();
    }
#pragma unroll
    for (int mi = 0; mi < 2; mi++) {
        int r0 = row0 + rowb + mi * 16 + gid;
#pragma unroll
        for (int ni = 0; ni < 4; ni++) {
            int c0 = cb + colb + ni * 8 + 2 * tig;
#pragma unroll
            for (int e = 0; e < 4; e++) {
                int gr = r0 + (e >> 1) * 8;
                int cc = c0 + (e & 1);
                if (cc < nseg) Cb[(long)gr * ldc + cc] = acc[mi][ni][e] + bias[cc];
            }
        }
    }
}

// ---------------- rigid transform ----------------
__global__ void rigid_kernel(const float* __restrict__ rot,
                             const float* __restrict__ trans)
{
    int idx = blockIdx.x * 256 + threadIdx.x;
    if (idx >= NN * 224) return;
    int n = idx / 224, p = idx % 224;
    const float* R = rot + n * 9;
    const float* T = trans + n * 3;
    float lx, ly, lz;
    if (p < 64) {
        lx = g_qpraw[n * 192 + p];
        ly = g_qpraw[n * 192 + 64 + p];
        lz = g_qpraw[n * 192 + 128 + p];
    } else {
        int pp = p - 64;
        lx = g_kvpraw[n * 480 + pp];
        ly = g_kvpraw[n * 480 + 160 + pp];
        lz = g_kvpraw[n * 480 + 320 + pp];
    }
    float gx = R[0]*lx + R[1]*ly + R[2]*lz + T[0];
    float gy = R[3]*lx + R[4]*ly + R[5]*lz + T[1];
    float gz = R[6]*lx + R[7]*ly + R[8]*lz + T[2];
    if (p < 64) {
        int h = p >> 3, pq = p & 7;
        float* d = g_qpts + n * 192 + h * 24 + pq * 3;
        d[0] = gx; d[1] = gy; d[2] = gz;
    } else {
        int pp = p - 64;
        int h = pp / 20, q = pp % 20;
        if (q < 8) {
            float* d = g_kpts + n * 192 + h * 24 + q * 3;
            d[0] = gx; d[1] = gy; d[2] = gz;
        } else {
            float* d = g_vpts + n * 288 + h * 36 + (q - 8) * 3;
            d[0] = gx; d[1] = gy; d[2] = gz;
        }
    }
}

// ---------------- per (n,h) point-norm sums (exact fp32) ----------------
__global__ void pnorm_kernel()
{
    int idx = blockIdx.x * 256 + threadIdx.x;
    if (idx >= NN * NH) return;
    int n = idx >> 3, h = idx & 7;
    float sq = 0.f, sk = 0.f;
#pragma unroll
    for (int d = 0; d < 24; d++) {
        float a = g_qpts[n * 192 + h * 24 + d];
        float b = g_kpts[n * 192 + h * 24 + d];
        sq += a * a; sk += b * b;
    }
    g_qnorm[idx] = sq; g_knorm[idx] = sk;
}

// ---------------- z projections: warp-autonomous cp.async streaming GEMM ----------------
// [262144 x 128] @ [128 x 40] -> biasz (cols 0..7) + pairz (cols 8..39)
// 128 pairs/block, each warp owns 16 rows end-to-end: private double-buffered
// cp.async staging, no block barriers in the main loop.
__global__ __launch_bounds__(256) void zproj_tc(const float* __restrict__ z,
                             const float* __restrict__ wb, const float* __restrict__ bb,
                             const float* __restrict__ wz)
{
    __shared__ float    As[8][2][16][36];  // 36.9 KB, per-warp double buffer
    __shared__ uint32_t Bs[128][40];       // 20.5 KB
    const int tid = threadIdx.x;
    const int lane = tid & 31, wrp = tid >> 5;
    const int gid = lane >> 2, tig = lane & 3;
    const long pair0 = (long)blockIdx.x * 128;
    const long row0 = pair0 + wrp * 16;    // this warp's 16 rows

    // stage weights once (block-wide), then one barrier
    for (int i = tid; i < 128 * 40; i += 256) {
        int k = i / 40, c = i % 40;
        float v = (c < 8) ? wb[k * 8 + c] : wz[k * 32 + (c - 8)];
        Bs[k][c] = to_tf32(v);
    }
    __syncthreads();

    // warp-private async stage of a 16x32 chunk:
    // 16 rows x 8 float4/row = 128 float4 slots, 32 lanes x 4 iters.
#define ZSTAGE(buf, k0)                                                        \
    {                                                                          \
        _Pragma("unroll")                                                      \
        for (int l = 0; l < 4; l++) {                                          \
            int q = lane + l * 32;                                             \
            int r = q >> 3, kq = q & 7;                                        \
            uint32_t dst = (uint32_t)__cvta_generic_to_shared(&As[wrp][buf][r][kq * 4]); \
            const float* src = z + (row0 + r) * 128 + (k0) + kq * 4;           \
            asm volatile("cp.async.cg.shared.global [%0], [%1], 16;" :: "r"(dst), "l"(src)); \
        }                                                                      \
        asm volatile("cp.async.commit_group;");                                \
    }

    ZSTAGE(0, 0);

    float acc[5][4];
#pragma unroll
    for (int ni = 0; ni < 5; ni++)
#pragma unroll
        for (int e = 0; e < 4; e++) acc[ni][e] = 0.f;

#pragma unroll
    for (int c = 0; c < 4; c++) {
        const int buf = c & 1;
        if (c < 3) ZSTAGE((c + 1) & 1, (c + 1) * 32);
        if (c < 3) { asm volatile("cp.async.wait_group 1;"); }
        else       { asm volatile("cp.async.wait_group 0;"); }
        __syncwarp();
#pragma unroll
        for (int kb = 0; kb < 32; kb += 8) {
            uint32_t af[4], bf[5][2];
            af[0] = __float_as_uint(As[wrp][buf][gid][kb + tig]);
            af[1] = __float_as_uint(As[wrp][buf][gid + 8][kb + tig]);
            af[2] = __float_as_uint(As[wrp][buf][gid][kb + tig + 4]);
            af[3] = __float_as_uint(As[wrp][buf][gid + 8][kb + tig + 4]);
#pragma unroll
            for (int ni = 0; ni < 5; ni++) {
                bf[ni][0] = Bs[c * 32 + kb + tig][ni * 8 + gid];
                bf[ni][1] = Bs[c * 32 + kb + tig + 4][ni * 8 + gid];
            }
#pragma unroll
            for (int ni = 0; ni < 5; ni++)
                mma_tf32(acc[ni], af, bf[ni]);
        }
        __syncwarp();  // all lanes done reading buf before it is restaged
    }
#undef ZSTAGE

#pragma unroll
    for (int ni = 0; ni < 5; ni++) {
#pragma unroll
        for (int e = 0; e < 4; e++) {
            long gp = row0 + gid + (e >> 1) * 8;
            int cc = ni * 8 + 2 * tig + (e & 1);
            float v = acc[ni][e];
            if (cc < 8) g_biasz[(long)cc * 262144 + gp] = v + bb[cc];
            else        g_pairz[gp * 32 + (cc - 8)] = v;
        }
    }
}

// ---------------- logits: tensor QK + 2xTF32 point cross-term ----------------
__global__ __launch_bounds__(256) void logits_tc(const float* __restrict__ mask,
                              const float* __restrict__ head_w)
{
    const int h = blockIdx.z;
    __shared__ uint32_t As[16][136];
    __shared__ uint32_t Bs[16][72];
    __shared__ float qn_s[128], kn_s[64], mi_s[128], mj_s[64];
    MMA_DECLS;
    const int row0 = blockIdx.y * 128;
    const int col0 = blockIdx.x * 64;

    float w = head_w[h];
    float sp = (w > 20.f) ? w : log1pf(__expf(w));
    const float hw = sp * 0.09622504486493762f;    // softplus * sqrt(1/108)
    const float qscale = 0.036084391824351615f;    // sqrt(1/768)

    if (tid < 128) { qn_s[tid] = g_qnorm[(row0 + tid) * 8 + h]; mi_s[tid] = mask[row0 + tid]; }
    else if (tid < 192) { int c = tid - 128; kn_s[c] = g_knorm[(col0 + c) * 8 + h]; mj_s[c] = mask[col0 + c]; }

    float acc[2][4][4], accP[2][4][4];
#pragma unroll
    for (int mi = 0; mi < 2; mi++)
#pragma unroll
        for (int ni = 0; ni < 4; ni++)
#pragma unroll
            for (int e = 0; e < 4; e++) { acc[mi][ni][e] = 0.f; accP[mi][ni][e] = 0.f; }

    // phase 1: 256-dim QK (q pre-scaled)
    for (int k0 = 0; k0 < 256; k0 += 16) {
#pragma unroll
        for (int i = 0; i < 8; i++) {
            int idx = tid + i * 256;
            int r = idx >> 4, kk = idx & 15;
            As[kk][r] = to_tf32(g_qbuf[(row0 + r) * 2048 + h * 256 + k0 + kk] * qscale);
        }
#pragma unroll
        for (int i = 0; i < 4; i++) {
            int idx = tid + i * 256;
            int c = idx >> 4, kk = idx & 15;
            Bs[kk][c] = to_tf32(g_kvbuf[(col0 + c) * 4096 + h * 512 + k0 + kk]);
        }
        __syncthreads();
        MMA_TILE(As, Bs, acc);
        __syncthreads();
    }
    // phase 2: point cross-term, 24 dims x (hi*hi + lo*hi + hi*lo) = 72 (pad 80)
    for (int k0 = 0; k0 < 80; k0 += 16) {
#pragma unroll
        for (int i = 0; i < 8; i++) {
            int idx = tid + i * 256;
            int r = idx >> 4, kk = idx & 15;
            int cc = k0 + kk;
            uint32_t v = 0u;
            if (cc < 72) {
                int sel = cc / 24, pd = cc % 24;
                float x = g_qpts[(row0 + r) * 192 + h * 24 + pd];
                float hi = tf32_hi(x);
                v = (sel == 1) ? to_tf32(x - hi) : __float_as_uint(hi);
            }
            As[kk][r] = v;
        }
#pragma unroll
        for (int i = 0; i < 4; i++) {
            int idx = tid + i * 256;
            int c = idx >> 4, kk = idx & 15;
            int cc = k0 + kk;
            uint32_t v = 0u;
            if (cc < 72) {
                int sel = cc / 24, pd = cc % 24;
                float x = g_kpts[(col0 + c) * 192 + h * 24 + pd];
                float hi = tf32_hi(x);
                v = (sel == 2) ? to_tf32(x - hi) : __float_as_uint(hi);
            }
            Bs[kk][c] = v;
        }
        __syncthreads();
        MMA_TILE(As, Bs, accP);
        __syncthreads();
    }

#pragma unroll
    for (int mi = 0; mi < 2; mi++) {
#pragma unroll
        for (int ni = 0; ni < 4; ni++) {
#pragma unroll
            for (int e = 0; e < 4; e++) {
                int lr = rowb + mi * 16 + gid + (e >> 1) * 8;
                int lc = colb + ni * 8 + 2 * tig + (e & 1);
                int gr = row0 + lr, gc = col0 + lc;
                float v = acc[mi][ni][e]
                        + hw * accP[mi][ni][e]
                        - 0.5f * hw * (qn_s[lr] + kn_s[lc])
                        + 0.5773502691896258f * g_biasz[(long)h * 262144 + gr * 512 + gc]
                        + 100000.0f * (mi_s[lr] * mj_s[lc] - 1.0f);
                g_logits[((long)h * 512 + gr) * 512 + gc] = v;
            }
        }
    }
}

// ---------------- warp-per-row softmax ----------------
__global__ void softmax_kernel()
{
    int row = blockIdx.x * 8 + (threadIdx.x >> 5);
    int lane = threadIdx.x & 31;
    float* r = g_logits + (long)row * 512;
    float v[16];
    float m = -1e30f;
#pragma unroll
    for (int i = 0; i < 16; i++) { v[i] = r[lane + i * 32]; m = fmaxf(m, v[i]); }
#pragma unroll
    for (int s = 16; s > 0; s >>= 1) m = fmaxf(m, __shfl_xor_sync(0xffffffff, m, s));
    float sum = 0.f;
#pragma unroll
    for (int i = 0; i < 16; i++) { v[i] = __expf(v[i] - m); sum += v[i]; }
#pragma unroll
    for (int s = 16; s > 0; s >>= 1) sum += __shfl_xor_sync(0xffffffff, sum, s);
    float inv = 1.0f / sum;
#pragma unroll
    for (int i = 0; i < 16; i++) r[lane + i * 32] = v[i] * inv;
}

// ---------------- o = a @ v (tensor) ----------------
__global__ __launch_bounds__(256) void av_tc()
{
    const int h = blockIdx.z;
    __shared__ uint32_t As[16][136];
    __shared__ uint32_t Bs[16][72];
    MMA_DECLS;
    const int row0 = blockIdx.y * 128;
    const int col0 = blockIdx.x * 64;

    float acc[2][4][4];
#pragma unroll
    for (int mi = 0; mi < 2; mi++)
#pragma unroll
        for (int ni = 0; ni < 4; ni++)
#pragma unroll
            for (int e = 0; e < 4; e++) acc[mi][ni][e] = 0.f;

    for (int k0 = 0; k0 < 512; k0 += 16) {
#pragma unroll
        for (int i = 0; i < 8; i++) {
            int idx = tid + i * 256;
            int r = idx >> 4, kk = idx & 15;
            As[kk][r] = to_tf32(g_logits[((long)h * 512 + row0 + r) * 512 + k0 + kk]);
        }
#pragma unroll
        for (int i = 0; i < 4; i++) {
            int idx = tid + i * 256;
            int kk = idx >> 6, c = idx & 63;
            Bs[kk][c] = to_tf32(g_kvbuf[(k0 + kk) * 4096 + h * 512 + 256 + col0 + c]);
        }
        __syncthreads();
        MMA_TILE(As, Bs, acc);
        __syncthreads();
    }
#pragma unroll
    for (int mi = 0; mi < 2; mi++) {
        int r0 = row0 + rowb + mi * 16 + gid;
#pragma unroll
        for (int ni = 0; ni < 4; ni++) {
            int c0 = col0 + colb + ni * 8 + 2 * tig;
#pragma unroll
            for (int e = 0; e < 4; e++) {
                int gr = r0 + (e >> 1) * 8;
                int cc = c0 + (e & 1);
                g_feats[(long)gr * FEAT + h * 256 + cc] = acc[mi][ni][e];
            }
        }
    }
}

// ---------------- o_pt = a @ v_pts (fp32, cancellation-sensitive) ----------------
__global__ __launch_bounds__(288) void optgemm_kernel()
{
    __shared__ float a_s[8][512];
    __shared__ float vs[128][36];
    const int h = blockIdx.y;
    const int i0 = blockIdx.x * 8;
    const int t = threadIdx.x;
    for (int idx = t; idx < 4096; idx += 288) {
        int r = idx >> 9, k = idx & 511;
        a_s[r][k] = g_logits[((long)h * 512 + i0 + r) * 512 + k];
    }
    const int r = t / 36, c = t % 36;
    float acc = 0.f;
    for (int kc = 0; kc < 512; kc += 128) {
        __syncthreads();
        for (int idx = t; idx < 128 * 36; idx += 288) {
            int rr = idx / 36, cc = idx % 36;
            vs[rr][cc] = g_vpts[(kc + rr) * 288 + h * 36 + cc];
        }
        __syncthreads();
#pragma unroll 8
        for (int kk = 0; kk < 128; kk++) acc += a_s[r][kc + kk] * vs[kk][c];
    }
    g_optbuf[((long)h * 512 + i0 + r) * 36 + c] = acc;
}

// ---------------- o_pair = a @ pairz + bz ----------------
__global__ __launch_bounds__(256) void opair_kernel(const float* __restrict__ bz)
{
    __shared__ float a_s[8][512];
    const int i = blockIdx.x;
    const int t = threadIdx.x;
    for (int idx = t; idx < 4096; idx += 256) {
        int h = idx >> 9, j = idx & 511;
        a_s[h][j] = g_logits[((long)h * 512 + i) * 512 + j];
    }
    __syncthreads();
    const int h = t >> 5, d = t & 31;
    const float* pz = g_pairz + (long)i * 512 * 32 + d;
    float acc = 0.f;
#pragma unroll 8
    for (int j = 0; j < 512; j++) acc += a_s[h][j] * pz[(long)j * 32];
    g_feats[(long)i * FEAT + 2432 + h * 32 + d] = acc + bz[d];
}

// ---------------- o_pt inverse rigid + norm ----------------
__global__ void optfinal_kernel(const float* __restrict__ rot,
                                const float* __restrict__ trans)
{
    int idx = blockIdx.x * 256 + threadIdx.x;
    if (idx >= NN * 96) return;
    int n = idx / 96, hp = idx % 96;
    int h = hp / 12, p = hp % 12;
    const float* o = g_optbuf + ((long)h * 512 + n) * 36 + p * 3;
    float x = o[0] - trans[n * 3 + 0];
    float y = o[1] - trans[n * 3 + 1];
    float zc = o[2] - trans[n * 3 + 2];
    const float* R = rot + n * 9;
    float ox = R[0] * x + R[3] * y + R[6] * zc;
    float oy = R[1] * x + R[4] * y + R[7] * zc;
    float oz = R[2] * x + R[5] * y + R[8] * zc;
    float* f = g_feats + (long)n * FEAT;
    f[2048 + 0 * 96 + hp] = ox;
    f[2048 + 1 * 96 + hp] = oy;
    f[2048 + 2 * 96 + hp] = oz;
    f[2336 + hp] = sqrtf(ox * ox + oy * oy + oz * oz + 1e-8f);
}

// ---------------- final GEMM (tensor, split-K=4) ----------------
__global__ __launch_bounds__(256) void fingemm_tc(const float* __restrict__ wo)
{
    __shared__ uint32_t As[16][136];
    __shared__ uint32_t Bs[16][72];
    MMA_DECLS;
    const int row0 = blockIdx.y * 128;
    const int col0 = blockIdx.x * 64;
    const int kz = blockIdx.z;
    float* C = g_part + (long)kz * NN * CS;

    float acc[2][4][4];
#pragma unroll
    for (int mi = 0; mi < 2; mi++)
#pragma unroll
        for (int ni = 0; ni < 4; ni++)
#pragma unroll
            for (int e = 0; e < 4; e++) acc[mi][ni][e] = 0.f;

    for (int k0 = kz * 672; k0 < kz * 672 + 672; k0 += 16) {
#pragma unroll
        for (int i = 0; i < 8; i++) {
            int idx = tid + i * 256;
            int r = idx >> 4, kk = idx & 15;
            As[kk][r] = to_tf32(g_feats[(long)(row0 + r) * FEAT + k0 + kk]);
        }
#pragma unroll
        for (int i = 0; i < 4; i++) {
            int idx = tid + i * 256;
            int kk = idx >> 6, c = idx & 63;
            Bs[kk][c] = to_tf32(wo[(long)(k0 + kk) * 384 + col0 + c]);
        }
        __syncthreads();
        MMA_TILE(As, Bs, acc);
        __syncthreads();
    }
#pragma unroll
    for (int mi = 0; mi < 2; mi++) {
        int r0 = row0 + rowb + mi * 16 + gid;
#pragma unroll
        for (int ni = 0; ni < 4; ni++) {
            int c0 = col0 + colb + ni * 8 + 2 * tig;
#pragma unroll
            for (int e = 0; e < 4; e++)
                C[(long)(r0 + (e >> 1) * 8) * 384 + c0 + (e & 1)] = acc[mi][ni][e];
        }
    }
}

__global__ void reduce_kernel(const float* __restrict__ bo, float* __restrict__ out)
{
    int idx = blockIdx.x * 256 + threadIdx.x;
    if (idx >= NN * CS) return;
    float v = bo[idx % 384];
#pragma unroll
    for (int zc = 0; zc < 4; zc++) v += g_part[(long)zc * NN * CS + idx];
    out[idx] = v;
}

// ---------------- launch ----------------
extern "C" void kernel_launch(void* const* d_in, const int* in_sizes, int n_in,
                              void* d_out, int out_size)
{
    const float* s     = (const float*)d_in[0];
    const float* z     = (const float*)d_in[1];
    const float* rot   = (const float*)d_in[2];
    const float* trans = (const float*)d_in[3];
    const float* mask  = (const float*)d_in[4];
    const float* wq    = (const float*)d_in[5];
    const float* bq    = (const float*)d_in[6];
    const float* wkv   = (const float*)d_in[7];
    const float* bkv   = (const float*)d_in[8];
    const float* wqp   = (const float*)d_in[9];
    const float* bqp   = (const float*)d_in[10];
    const float* wkvp  = (const float*)d_in[11];
    const float* bkvp  = (const float*)d_in[12];
    const float* wb    = (const float*)d_in[13];
    const float* bb    = (const float*)d_in[14];
    const float* wz    = (const float*)d_in[15];
    const float* bz    = (const float*)d_in[16];
    const float* hwt   = (const float*)d_in[17];
    const float* wo    = (const float*)d_in[18];
    const float* bo    = (const float*)d_in[19];
    float* out = (float*)d_out;

    proj_tc<<<dim3(107, 4), 256>>>(s, wq, bq, wkv, bkv, wqp, bqp, wkvp, bkvp);
    rigid_kernel<<<(NN * 224 + 255) / 256, 256>>>(rot, trans);
    pnorm_kernel<<<(NN * NH + 255) / 256, 256>>>();
    zproj_tc<<<2048, 256>>>(z, wb, bb, wz);
    logits_tc<<<dim3(8, 4, 8), 256>>>(mask, hwt);
    softmax_kernel<<<512, 256>>>();
    av_tc<<<dim3(4, 4, 8), 256>>>();
    optgemm_kernel<<<dim3(64, 8), 288>>>();
    opair_kernel<<<NN, 256>>>(bz);
    optfinal_kernel<<<(NN * 96 + 255) / 256, 256>>>(rot, trans);
    fingemm_tc<<<dim3(6, 4, 4), 256>>>(wo);
    reduce_kernel<<<(NN * CS + 255) / 256, 256>>>(bo, out);
}